// round 4
// baseline (speedup 1.0000x reference)
#include <cuda_runtime.h>
#include <cuda_bf16.h>
#include <cstdint>

// Problem constants
#define Bb 8
#define LL 1024
#define HH 8
#define EE 64
#define DD 64
#define SCALE 0.125f   // 1/sqrt(64)

// Output layout (concatenated flattened tuple):
//   V:      (B,L,H,D)   at 0              size 4,194,304
//   series: (B,H,L,S)   at 4,194,304      size 67,108,864
//   prior:  (B,L,S)     at 71,303,168     size 8,388,608
#define OFF_SERIES 4194304
#define OFF_PRIOR  71303168

// Scratch: per-(b,h,row,ntile) partial row sums of unnormalized exp scores.
__device__ float g_partial[Bb * HH * LL * 8];  // 2 MB

// ---- packed f32x2 helpers (sm_10x FFMA2) ----------------------------------
__device__ __forceinline__ unsigned long long dup2(float x) {
    unsigned long long r;
    unsigned u = __float_as_uint(x);
    asm("mov.b64 %0, {%1, %1};" : "=l"(r) : "r"(u));
    return r;
}
__device__ __forceinline__ void ffma2(unsigned long long& d,
                                      unsigned long long a,
                                      unsigned long long b) {
    asm("fma.rn.f32x2 %0, %1, %2, %3;" : "=l"(d) : "l"(a), "l"(b), "l"(d));
}
__device__ __forceinline__ float2 unpk(unsigned long long v) {
    unsigned lo, hi;
    asm("mov.b64 {%0, %1}, %2;" : "=r"(lo), "=r"(hi) : "l"(v));
    return make_float2(__uint_as_float(lo), __uint_as_float(hi));
}

// ---------------------------------------------------------------------------
// Kernel 1: E = exp(scale * Q K^T) for causal (lower-triangular) tiles.
// grid = (nt=8, mt=8, bh=64), block = 256, tile 128x128, micro 8x8,
// FFMA2 mainloop (pairs along the 8-wide v axis; a duplicated per pair).
// ---------------------------------------------------------------------------
__global__ __launch_bounds__(256, 2)
void k_scores(const float* __restrict__ Q, const float* __restrict__ K,
              float* __restrict__ series) {
    const int nt = blockIdx.x;
    const int mt = blockIdx.y;
    const int bh = blockIdx.z;          // b*8 + h
    const int b  = bh >> 3;
    const int h  = bh & 7;
    const int tid = threadIdx.x;
    const int tx = tid & 15;
    const int ty = tid >> 4;

    float* S = series + (size_t)bh * LL * LL;
    const int row0 = mt * 128, col0 = nt * 128;

    if (nt > mt) {
        const float4 z = make_float4(0.f, 0.f, 0.f, 0.f);
        #pragma unroll
        for (int i = 0; i < 16; i++) {
            int flat = i * 256 + tid;
            int r = flat >> 5;
            int c = (flat & 31) << 2;
            *(float4*)(S + (size_t)(row0 + r) * LL + col0 + c) = z;
        }
        return;
    }

    __shared__ __align__(16) float Qs[32][132];
    __shared__ __align__(16) float Ks[32][132];

    unsigned long long acc2[8][4];   // [u row][v-pair], f32x2 accumulators
    #pragma unroll
    for (int u = 0; u < 8; u++)
        #pragma unroll
        for (int j = 0; j < 4; j++) acc2[u][j] = 0ull;

    const float* Qg = Q + (size_t)b * LL * (HH * EE) + h * EE;  // + l*512 + e
    const float* Kg = K + (size_t)b * LL * (HH * EE) + h * EE;

    for (int kk = 0; kk < EE; kk += 32) {
        // cooperative transposed loads, lanes along contiguous e-axis;
        // stored column swizzled: mc = m ^ (4*c4)
        #pragma unroll
        for (int it = 0; it < 4; it++) {
            int flat = it * 256 + tid;     // 1024 float4 per matrix
            int c4 = flat & 7;
            int m  = flat >> 3;
            int mc = m ^ (c4 * 4);
            float4 v = *(const float4*)(Qg + (size_t)(row0 + m) * 512 + kk + c4 * 4);
            Qs[c4 * 4 + 0][mc] = v.x; Qs[c4 * 4 + 1][mc] = v.y;
            Qs[c4 * 4 + 2][mc] = v.z; Qs[c4 * 4 + 3][mc] = v.w;
            float4 w = *(const float4*)(Kg + (size_t)(col0 + m) * 512 + kk + c4 * 4);
            Ks[c4 * 4 + 0][mc] = w.x; Ks[c4 * 4 + 1][mc] = w.y;
            Ks[c4 * 4 + 2][mc] = w.z; Ks[c4 * 4 + 3][mc] = w.w;
        }
        __syncthreads();

        #pragma unroll 4
        for (int k = 0; k < 32; k++) {
            const int s4 = k & 28;                 // 4*(k>>2)
            const int ab  = (ty * 4) ^ s4;
            const int bb0 = (tx * 4) ^ s4;
            float4 aA = *(const float4*)(&Qs[k][ab]);
            float4 aB = *(const float4*)(&Qs[k][ab + 64]);
            ulonglong2 bA = *(const ulonglong2*)(&Ks[k][bb0]);       // v-pairs 0,1
            ulonglong2 bB = *(const ulonglong2*)(&Ks[k][bb0 + 64]);  // v-pairs 2,3
            float av[8] = {aA.x, aA.y, aA.z, aA.w, aB.x, aB.y, aB.z, aB.w};
            #pragma unroll
            for (int u = 0; u < 8; u++) {
                unsigned long long a2 = dup2(av[u]);
                ffma2(acc2[u][0], a2, bA.x);
                ffma2(acc2[u][1], a2, bA.y);
                ffma2(acc2[u][2], a2, bB.x);
                ffma2(acc2[u][3], a2, bB.y);
            }
        }
        __syncthreads();
    }

    // mask + exp + write + tile-row sums
    // rows: u<4 -> ty*4+u ; u>=4 -> 64+ty*4+(u-4)
    // cols: v<4 -> tx*4+v ; v>=4 -> 64+tx*4+(v-4)
    const int lane = tid & 31;
    #pragma unroll
    for (int u = 0; u < 8; u++) {
        const int row = row0 + ty * 4 + ((u < 4) ? u : 64 + (u - 4));
        float2 p0 = unpk(acc2[u][0]);
        float2 p1 = unpk(acc2[u][1]);
        float2 p2 = unpk(acc2[u][2]);
        float2 p3 = unpk(acc2[u][3]);
        float e[8] = {p0.x, p0.y, p1.x, p1.y, p2.x, p2.y, p3.x, p3.y};
        float rsum = 0.f;
        #pragma unroll
        for (int v = 0; v < 8; v++) {
            const int col = col0 + tx * 4 + ((v < 4) ? v : 64 + (v - 4));
            e[v] = (col <= row) ? __expf(SCALE * e[v]) : 0.f;
            rsum += e[v];
        }
        #pragma unroll
        for (int off = 1; off < 16; off <<= 1)
            rsum += __shfl_xor_sync(0xffffffffu, rsum, off);
        if ((lane & 15) == 0)
            g_partial[((size_t)bh * LL + row) * 8 + nt] = rsum;

        float* dst = S + (size_t)row * LL + col0 + tx * 4;
        *(float4*)dst        = make_float4(e[0], e[1], e[2], e[3]);
        *(float4*)(dst + 64) = make_float4(e[4], e[5], e[6], e[7]);
    }
}

// ---------------------------------------------------------------------------
// Kernel 2: normalize series in-place (P = E / rowsum) and O = P @ V.
// grid = (pair=4, bh=64): each CTA handles output tiles mt=x and mt=7-x
// (combined causal work = 9 chunks, perfectly balanced; 256 CTAs = 1 wave).
// FFMA2 mainloop: a-fragments read as ready f32x2 pairs, b duplicated.
// ---------------------------------------------------------------------------
__global__ __launch_bounds__(256, 2)
void k_av(const float* __restrict__ V, float* __restrict__ series,
          float* __restrict__ outV) {
    const int bh = blockIdx.y;
    const int b  = bh >> 3;
    const int h  = bh & 7;
    const int tid = threadIdx.x;
    const int tx = tid & 15;     // d group (4 cols)
    const int ty = tid >> 4;     // m group (8 rows)

    __shared__ float rinv[128];
    __shared__ __align__(16) float Ps[32][132];  // [s][m], swizzled cols
    __shared__ __align__(16) float Vs[32][68];   // [s][d]

    float* S = series + (size_t)bh * LL * LL;
    const float* Vg = V + (size_t)b * LL * (HH * DD) + h * DD;

    const int mts[2] = { (int)blockIdx.x, 7 - (int)blockIdx.x };

    #pragma unroll 1
    for (int t = 0; t < 2; t++) {
        const int mt = mts[t];
        const int row0 = mt * 128;

        if (tid < 128) {
            float s = 0.f;
            for (int nt = 0; nt <= mt; nt++)
                s += g_partial[((size_t)bh * LL + row0 + tid) * 8 + nt];
            rinv[tid] = 1.0f / s;
        }
        __syncthreads();

        unsigned long long acc2[4][4];   // [u-pair][v], rows paired
        #pragma unroll
        for (int up = 0; up < 4; up++)
            #pragma unroll
            for (int v = 0; v < 4; v++) acc2[up][v] = 0ull;

        for (int nt = mt; nt >= 0; nt--) {
            for (int sc = 0; sc < 128; sc += 32) {
                const int s0 = nt * 128 + sc;
                // load E chunk (coalesced), normalize, write back P,
                // stage transposed+swizzled in smem
                #pragma unroll
                for (int it = 0; it < 4; it++) {
                    int flat = it * 256 + tid;   // 1024 float4
                    int c4 = flat & 7;
                    int m  = flat >> 3;
                    int mc = m ^ (c4 * 4);
                    float* g = S + (size_t)(row0 + m) * LL + s0 + c4 * 4;
                    float4 v = *(float4*)g;
                    float r = rinv[m];
                    v.x *= r; v.y *= r; v.z *= r; v.w *= r;
                    *(float4*)g = v;
                    Ps[c4 * 4 + 0][mc] = v.x; Ps[c4 * 4 + 1][mc] = v.y;
                    Ps[c4 * 4 + 2][mc] = v.z; Ps[c4 * 4 + 3][mc] = v.w;
                }
                // load V chunk [32 s][64 d]
                #pragma unroll
                for (int it = 0; it < 2; it++) {
                    int flat = it * 256 + tid;   // 512 float4
                    int sr = flat >> 4;
                    int d4 = (flat & 15) << 2;
                    *(float4*)&Vs[sr][d4] =
                        *(const float4*)(Vg + (size_t)(s0 + sr) * 512 + d4);
                }
                __syncthreads();

                #pragma unroll 4
                for (int k = 0; k < 32; k++) {
                    const int s4 = k & 28;
                    const int i0 = (ty * 8) ^ s4;
                    const int i1 = (ty * 8 + 4) ^ s4;
                    ulonglong2 aA = *(const ulonglong2*)(&Ps[k][i0]); // rows (0,1),(2,3)
                    ulonglong2 aB = *(const ulonglong2*)(&Ps[k][i1]); // rows (4,5),(6,7)
                    float4 bvv = *(const float4*)(&Vs[k][tx * 4]);
                    unsigned long long bd0 = dup2(bvv.x);
                    unsigned long long bd1 = dup2(bvv.y);
                    unsigned long long bd2 = dup2(bvv.z);
                    unsigned long long bd3 = dup2(bvv.w);
                    unsigned long long ap[4] = {aA.x, aA.y, aB.x, aB.y};
                    #pragma unroll
                    for (int up = 0; up < 4; up++) {
                        ffma2(acc2[up][0], ap[up], bd0);
                        ffma2(acc2[up][1], ap[up], bd1);
                        ffma2(acc2[up][2], ap[up], bd2);
                        ffma2(acc2[up][3], ap[up], bd3);
                    }
                }
                __syncthreads();
            }
        }

        float* Og = outV + (size_t)b * LL * (HH * DD) + h * DD;
        #pragma unroll
        for (int up = 0; up < 4; up++) {
            float2 c0 = unpk(acc2[up][0]);
            float2 c1 = unpk(acc2[up][1]);
            float2 c2 = unpk(acc2[up][2]);
            float2 c3 = unpk(acc2[up][3]);
            const int rowA = row0 + ty * 8 + up * 2;
            *(float4*)(Og + (size_t)rowA * 512 + tx * 4) =
                make_float4(c0.x, c1.x, c2.x, c3.x);
            *(float4*)(Og + (size_t)(rowA + 1) * 512 + tx * 4) =
                make_float4(c0.y, c1.y, c2.y, c3.y);
        }
    }
}

// ---------------------------------------------------------------------------
// Kernel 3: prior association (MUFU-bound, ~20us; unchanged).
// ---------------------------------------------------------------------------
__global__ __launch_bounds__(256)
void k_prior(const float* __restrict__ sigma, float* __restrict__ prior) {
    const int b  = blockIdx.y;
    const int i0 = blockIdx.x * 32;
    const int tid = threadIdx.x;

    __shared__ float rl[8][1024];    // -1/sigma[b,h,s]
    __shared__ float red[8];

    for (int idx = tid; idx < 8 * 1024; idx += 256) {
        int h = idx >> 10;
        int s = idx & 1023;
        rl[h][s] = -1.0f / sigma[((size_t)b * 8 + h) * 1024 + s];
    }
    __syncthreads();

    const int lane = tid & 31, wid = tid >> 5;

    for (int ii = 0; ii < 32; ii++) {
        const int i = i0 + ii;
        float p[4];
        float sum = 0.f;
        #pragma unroll
        for (int j = 0; j < 4; j++) {
            const int s = tid + j * 256;
            const float d = (float)((i > s) ? (i - s) : (s - i));
            float a = 0.f;
            #pragma unroll
            for (int h = 0; h < 8; h++)
                a += __expf(d * rl[h][s]);
            p[j] = a;
            sum += a;
        }
        #pragma unroll
        for (int off = 16; off; off >>= 1)
            sum += __shfl_xor_sync(0xffffffffu, sum, off);
        if (lane == 0) red[wid] = sum;
        __syncthreads();
        float tot = 0.f;
        #pragma unroll
        for (int w = 0; w < 8; w++) tot += red[w];
        const float inv = 1.0f / tot;
        float* dst = prior + (size_t)(b * 1024 + i) * 1024;
        #pragma unroll
        for (int j = 0; j < 4; j++)
            dst[tid + j * 256] = p[j] * inv;
        __syncthreads();
    }
}

// ---------------------------------------------------------------------------
extern "C" void kernel_launch(void* const* d_in, const int* in_sizes, int n_in,
                              void* d_out, int out_size) {
    (void)in_sizes; (void)n_in; (void)out_size;
    const float* Q   = (const float*)d_in[0];
    const float* K   = (const float*)d_in[1];
    const float* V   = (const float*)d_in[2];
    const float* sig = (const float*)d_in[3];
    float* out    = (float*)d_out;
    float* outV   = out;                 // (B,L,H,D)
    float* series = out + OFF_SERIES;    // (B,H,L,S)
    float* prior  = out + OFF_PRIOR;     // (B,L,S)

    k_scores<<<dim3(8, 8, Bb * HH), 256>>>(Q, K, series);
    k_av    <<<dim3(4, Bb * HH),   256>>>(V, series, outV);
    k_prior <<<dim3(32, Bb),       256>>>(sig, prior);
}

// round 5
// speedup vs baseline: 1.4613x; 1.4613x over previous
#include <cuda_runtime.h>
#include <cuda_bf16.h>
#include <cstdint>

// Problem constants
#define Bb 8
#define LL 1024
#define HH 8
#define EE 64
#define DD 64
#define SCALE 0.125f   // 1/sqrt(64)

// Output layout (concatenated flattened tuple):
//   V:      (B,L,H,D)   at 0              size 4,194,304
//   series: (B,H,L,S)   at 4,194,304      size 67,108,864
//   prior:  (B,L,S)     at 71,303,168     size 8,388,608
#define OFF_SERIES 4194304
#define OFF_PRIOR  71303168

// Scratch: per-(b,h,row,ntile) partial row sums of unnormalized exp scores.
__device__ float g_partial[Bb * HH * LL * 8];  // 2 MB

// ---------------------------------------------------------------------------
// Kernel 1: E = exp(scale * Q K^T) for causal (lower-triangular) tiles.
// grid = (nt=8, mt=8, bh=64), block = 256, tile 128x128, micro 8x8 with
// stride-64 split fragments (conflict-free LDS) and xor-swizzled smem
// staging (conflict-free STS). Scalar FFMA mainloop (dual-pipe issue).
// ---------------------------------------------------------------------------
__global__ __launch_bounds__(256, 2)
void k_scores(const float* __restrict__ Q, const float* __restrict__ K,
              float* __restrict__ series) {
    const int nt = blockIdx.x;
    const int mt = blockIdx.y;
    const int bh = blockIdx.z;          // b*8 + h
    const int b  = bh >> 3;
    const int h  = bh & 7;
    const int tid = threadIdx.x;
    const int tx = tid & 15;
    const int ty = tid >> 4;

    float* S = series + (size_t)bh * LL * LL;
    const int row0 = mt * 128, col0 = nt * 128;

    if (nt > mt) {
        const float4 z = make_float4(0.f, 0.f, 0.f, 0.f);
        #pragma unroll
        for (int i = 0; i < 16; i++) {
            int flat = i * 256 + tid;
            int r = flat >> 5;
            int c = (flat & 31) << 2;
            *(float4*)(S + (size_t)(row0 + r) * LL + col0 + c) = z;
        }
        return;
    }

    __shared__ __align__(16) float Qs[32][132];
    __shared__ __align__(16) float Ks[32][132];

    float acc[8][8];
    #pragma unroll
    for (int u = 0; u < 8; u++)
        #pragma unroll
        for (int v = 0; v < 8; v++) acc[u][v] = 0.f;

    const float* Qg = Q + (size_t)b * LL * (HH * EE) + h * EE;  // + l*512 + e
    const float* Kg = K + (size_t)b * LL * (HH * EE) + h * EE;

    for (int kk = 0; kk < EE; kk += 32) {
        // cooperative transposed loads, lanes along contiguous e-axis;
        // stored column swizzled: mc = m ^ (4*c4)  (c4 = krow>>2)
        #pragma unroll
        for (int it = 0; it < 4; it++) {
            int flat = it * 256 + tid;     // 1024 float4 per matrix
            int c4 = flat & 7;
            int m  = flat >> 3;
            int mc = m ^ (c4 * 4);
            float4 v = *(const float4*)(Qg + (size_t)(row0 + m) * 512 + kk + c4 * 4);
            Qs[c4 * 4 + 0][mc] = v.x; Qs[c4 * 4 + 1][mc] = v.y;
            Qs[c4 * 4 + 2][mc] = v.z; Qs[c4 * 4 + 3][mc] = v.w;
            float4 w = *(const float4*)(Kg + (size_t)(col0 + m) * 512 + kk + c4 * 4);
            Ks[c4 * 4 + 0][mc] = w.x; Ks[c4 * 4 + 1][mc] = w.y;
            Ks[c4 * 4 + 2][mc] = w.z; Ks[c4 * 4 + 3][mc] = w.w;
        }
        __syncthreads();

        #pragma unroll 4
        for (int k = 0; k < 32; k++) {
            const int s4 = k & 28;                 // 4*(k>>2)
            const int ab = (ty * 4) ^ s4;          // a base col (row index m)
            const int bb0 = (tx * 4) ^ s4;         // b base
            float a[8], bv[8];
            *(float4*)(&a[0])  = *(const float4*)(&Qs[k][ab]);
            *(float4*)(&a[4])  = *(const float4*)(&Qs[k][ab + 64]);
            *(float4*)(&bv[0]) = *(const float4*)(&Ks[k][bb0]);
            *(float4*)(&bv[4]) = *(const float4*)(&Ks[k][bb0 + 64]);
            #pragma unroll
            for (int u = 0; u < 8; u++)
                #pragma unroll
                for (int v = 0; v < 8; v++)
                    acc[u][v] = fmaf(a[u], bv[v], acc[u][v]);
        }
        __syncthreads();
    }

    // mask + exp + write + tile-row sums
    // rows: u<4 -> ty*4+u ; u>=4 -> 64+ty*4+(u-4)
    // cols: v<4 -> tx*4+v ; v>=4 -> 64+tx*4+(v-4)
    const int lane = tid & 31;
    #pragma unroll
    for (int u = 0; u < 8; u++) {
        const int row = row0 + ty * 4 + ((u < 4) ? u : 64 + (u - 4));
        float rsum = 0.f;
        #pragma unroll
        for (int v = 0; v < 8; v++) {
            const int col = col0 + tx * 4 + ((v < 4) ? v : 64 + (v - 4));
            float e = (col <= row) ? __expf(SCALE * acc[u][v]) : 0.f;
            acc[u][v] = e;
            rsum += e;
        }
        // threads sharing this row = the 16 tx lanes of this half-warp
        #pragma unroll
        for (int off = 1; off < 16; off <<= 1)
            rsum += __shfl_xor_sync(0xffffffffu, rsum, off);
        if ((lane & 15) == 0)
            g_partial[((size_t)bh * LL + row) * 8 + nt] = rsum;

        float* dst = S + (size_t)row * LL + col0 + tx * 4;
        *(float4*)dst        = make_float4(acc[u][0], acc[u][1], acc[u][2], acc[u][3]);
        *(float4*)(dst + 64) = make_float4(acc[u][4], acc[u][5], acc[u][6], acc[u][7]);
    }
}

// ---------------------------------------------------------------------------
// Kernel 2: normalize series in-place (P = E / rowsum) and O = P @ V.
// grid = (pair=4, bh=64): each CTA handles output tiles mt=x and mt=7-x
// (combined causal work = 9 chunks, perfectly balanced; 256 CTAs = 1 wave).
// Scalar FFMA mainloop, swizzled Ps staging.
// ---------------------------------------------------------------------------
__global__ __launch_bounds__(256, 2)
void k_av(const float* __restrict__ V, float* __restrict__ series,
          float* __restrict__ outV) {
    const int bh = blockIdx.y;
    const int b  = bh >> 3;
    const int h  = bh & 7;
    const int tid = threadIdx.x;
    const int tx = tid & 15;     // d group (4 cols)
    const int ty = tid >> 4;     // m group (8 rows)

    __shared__ float rinv[128];
    __shared__ __align__(16) float Ps[32][132];  // [s][m], swizzled cols
    __shared__ __align__(16) float Vs[32][68];   // [s][d]

    float* S = series + (size_t)bh * LL * LL;
    const float* Vg = V + (size_t)b * LL * (HH * DD) + h * DD;

    const int mts[2] = { (int)blockIdx.x, 7 - (int)blockIdx.x };

    #pragma unroll 1
    for (int t = 0; t < 2; t++) {
        const int mt = mts[t];
        const int row0 = mt * 128;

        if (tid < 128) {
            float s = 0.f;
            for (int nt = 0; nt <= mt; nt++)
                s += g_partial[((size_t)bh * LL + row0 + tid) * 8 + nt];
            rinv[tid] = 1.0f / s;
        }
        __syncthreads();

        float acc[8][4];
        #pragma unroll
        for (int u = 0; u < 8; u++)
            #pragma unroll
            for (int v = 0; v < 4; v++) acc[u][v] = 0.f;

        for (int nt = mt; nt >= 0; nt--) {
            for (int sc = 0; sc < 128; sc += 32) {
                const int s0 = nt * 128 + sc;
                // load E chunk (coalesced), normalize, write back P,
                // stage transposed+swizzled in smem
                #pragma unroll
                for (int it = 0; it < 4; it++) {
                    int flat = it * 256 + tid;   // 1024 float4
                    int c4 = flat & 7;
                    int m  = flat >> 3;
                    int mc = m ^ (c4 * 4);
                    float* g = S + (size_t)(row0 + m) * LL + s0 + c4 * 4;
                    float4 v = *(float4*)g;
                    float r = rinv[m];
                    v.x *= r; v.y *= r; v.z *= r; v.w *= r;
                    *(float4*)g = v;
                    Ps[c4 * 4 + 0][mc] = v.x; Ps[c4 * 4 + 1][mc] = v.y;
                    Ps[c4 * 4 + 2][mc] = v.z; Ps[c4 * 4 + 3][mc] = v.w;
                }
                // load V chunk [32 s][64 d]
                #pragma unroll
                for (int it = 0; it < 2; it++) {
                    int flat = it * 256 + tid;   // 512 float4
                    int sr = flat >> 4;
                    int d4 = (flat & 15) << 2;
                    *(float4*)&Vs[sr][d4] =
                        *(const float4*)(Vg + (size_t)(s0 + sr) * 512 + d4);
                }
                __syncthreads();

                #pragma unroll 4
                for (int k = 0; k < 32; k++) {
                    const int s4 = k & 28;
                    const int i0 = (ty * 8) ^ s4;
                    const int i1 = (ty * 8 + 4) ^ s4;
                    float a[8], bv[4];
                    *(float4*)(&a[0]) = *(const float4*)(&Ps[k][i0]);
                    *(float4*)(&a[4]) = *(const float4*)(&Ps[k][i1]);
                    *(float4*)(&bv[0]) = *(const float4*)(&Vs[k][tx * 4]);
                    #pragma unroll
                    for (int u = 0; u < 8; u++)
                        #pragma unroll
                        for (int v = 0; v < 4; v++)
                            acc[u][v] = fmaf(a[u], bv[v], acc[u][v]);
                }
                __syncthreads();
            }
        }

        float* Og = outV + (size_t)b * LL * (HH * DD) + h * DD;
        #pragma unroll
        for (int u = 0; u < 8; u++) {
            const int row = row0 + ty * 8 + u;
            *(float4*)(Og + (size_t)row * 512 + tx * 4) =
                make_float4(acc[u][0], acc[u][1], acc[u][2], acc[u][3]);
        }
    }
}

// ---------------------------------------------------------------------------
// Kernel 3: prior association (MUFU-bound, ~20us; unchanged).
// ---------------------------------------------------------------------------
__global__ __launch_bounds__(256)
void k_prior(const float* __restrict__ sigma, float* __restrict__ prior) {
    const int b  = blockIdx.y;
    const int i0 = blockIdx.x * 32;
    const int tid = threadIdx.x;

    __shared__ float rl[8][1024];    // -1/sigma[b,h,s]
    __shared__ float red[8];

    for (int idx = tid; idx < 8 * 1024; idx += 256) {
        int h = idx >> 10;
        int s = idx & 1023;
        rl[h][s] = -1.0f / sigma[((size_t)b * 8 + h) * 1024 + s];
    }
    __syncthreads();

    const int lane = tid & 31, wid = tid >> 5;

    for (int ii = 0; ii < 32; ii++) {
        const int i = i0 + ii;
        float p[4];
        float sum = 0.f;
        #pragma unroll
        for (int j = 0; j < 4; j++) {
            const int s = tid + j * 256;
            const float d = (float)((i > s) ? (i - s) : (s - i));
            float a = 0.f;
            #pragma unroll
            for (int h = 0; h < 8; h++)
                a += __expf(d * rl[h][s]);
            p[j] = a;
            sum += a;
        }
        #pragma unroll
        for (int off = 16; off; off >>= 1)
            sum += __shfl_xor_sync(0xffffffffu, sum, off);
        if (lane == 0) red[wid] = sum;
        __syncthreads();
        float tot = 0.f;
        #pragma unroll
        for (int w = 0; w < 8; w++) tot += red[w];
        const float inv = 1.0f / tot;
        float* dst = prior + (size_t)(b * 1024 + i) * 1024;
        #pragma unroll
        for (int j = 0; j < 4; j++)
            dst[tid + j * 256] = p[j] * inv;
        __syncthreads();
    }
}

// ---------------------------------------------------------------------------
extern "C" void kernel_launch(void* const* d_in, const int* in_sizes, int n_in,
                              void* d_out, int out_size) {
    (void)in_sizes; (void)n_in; (void)out_size;
    const float* Q   = (const float*)d_in[0];
    const float* K   = (const float*)d_in[1];
    const float* V   = (const float*)d_in[2];
    const float* sig = (const float*)d_in[3];
    float* out    = (float*)d_out;
    float* outV   = out;                 // (B,L,H,D)
    float* series = out + OFF_SERIES;    // (B,H,L,S)
    float* prior  = out + OFF_PRIOR;     // (B,L,S)

    k_scores<<<dim3(8, 8, Bb * HH), 256>>>(Q, K, series);
    k_av    <<<dim3(4, Bb * HH),   256>>>(V, series, outV);
    k_prior <<<dim3(32, Bb),       256>>>(sig, prior);
}

// round 8
// speedup vs baseline: 1.6488x; 1.1283x over previous
#include <cuda_runtime.h>
#include <cuda_bf16.h>
#include <cstdint>

// Problem constants
#define Bb 8
#define LL 1024
#define HH 8
#define EE 64
#define DD 64
#define SCALE 0.125f   // 1/sqrt(64)

// Output layout (concatenated flattened tuple):
//   V:      (B,L,H,D)   at 0              size 4,194,304
//   series: (B,H,L,S)   at 4,194,304      size 67,108,864
//   prior:  (B,L,S)     at 71,303,168     size 8,388,608
#define OFF_SERIES 4194304
#define OFF_PRIOR  71303168

// Scratch: per-(b,h,row,ntile) partial row sums of unnormalized exp scores.
__device__ float g_partial[Bb * HH * LL * 8];  // 2 MB

// ---------------------------------------------------------------------------
// Kernel 1: E = exp(scale * Q K^T) for causal (lower-triangular) tiles.
// grid = (nt=8, mt=8, bh=64), block = 256, tile 128x128, micro 8x8 with
// stride-64 split fragments + xor-swizzled smem staging (conflict-free).
// Issue-bound at the SIMT FFMA ceiling (~134us). (unchanged from R5)
// ---------------------------------------------------------------------------
__global__ __launch_bounds__(256, 2)
void k_scores(const float* __restrict__ Q, const float* __restrict__ K,
              float* __restrict__ series) {
    const int nt = blockIdx.x;
    const int mt = blockIdx.y;
    const int bh = blockIdx.z;          // b*8 + h
    const int b  = bh >> 3;
    const int h  = bh & 7;
    const int tid = threadIdx.x;
    const int tx = tid & 15;
    const int ty = tid >> 4;

    float* S = series + (size_t)bh * LL * LL;
    const int row0 = mt * 128, col0 = nt * 128;

    if (nt > mt) {
        const float4 z = make_float4(0.f, 0.f, 0.f, 0.f);
        #pragma unroll
        for (int i = 0; i < 16; i++) {
            int flat = i * 256 + tid;
            int r = flat >> 5;
            int c = (flat & 31) << 2;
            *(float4*)(S + (size_t)(row0 + r) * LL + col0 + c) = z;
        }
        return;
    }

    __shared__ __align__(16) float Qs[32][132];
    __shared__ __align__(16) float Ks[32][132];

    float acc[8][8];
    #pragma unroll
    for (int u = 0; u < 8; u++)
        #pragma unroll
        for (int v = 0; v < 8; v++) acc[u][v] = 0.f;

    const float* Qg = Q + (size_t)b * LL * (HH * EE) + h * EE;  // + l*512 + e
    const float* Kg = K + (size_t)b * LL * (HH * EE) + h * EE;

    for (int kk = 0; kk < EE; kk += 32) {
        #pragma unroll
        for (int it = 0; it < 4; it++) {
            int flat = it * 256 + tid;     // 1024 float4 per matrix
            int c4 = flat & 7;
            int m  = flat >> 3;
            int mc = m ^ (c4 * 4);
            float4 v = *(const float4*)(Qg + (size_t)(row0 + m) * 512 + kk + c4 * 4);
            Qs[c4 * 4 + 0][mc] = v.x; Qs[c4 * 4 + 1][mc] = v.y;
            Qs[c4 * 4 + 2][mc] = v.z; Qs[c4 * 4 + 3][mc] = v.w;
            float4 w = *(const float4*)(Kg + (size_t)(col0 + m) * 512 + kk + c4 * 4);
            Ks[c4 * 4 + 0][mc] = w.x; Ks[c4 * 4 + 1][mc] = w.y;
            Ks[c4 * 4 + 2][mc] = w.z; Ks[c4 * 4 + 3][mc] = w.w;
        }
        __syncthreads();

        #pragma unroll 4
        for (int k = 0; k < 32; k++) {
            const int s4 = k & 28;
            const int ab = (ty * 4) ^ s4;
            const int bb0 = (tx * 4) ^ s4;
            float a[8], bv[8];
            *(float4*)(&a[0])  = *(const float4*)(&Qs[k][ab]);
            *(float4*)(&a[4])  = *(const float4*)(&Qs[k][ab + 64]);
            *(float4*)(&bv[0]) = *(const float4*)(&Ks[k][bb0]);
            *(float4*)(&bv[4]) = *(const float4*)(&Ks[k][bb0 + 64]);
            #pragma unroll
            for (int u = 0; u < 8; u++)
                #pragma unroll
                for (int v = 0; v < 8; v++)
                    acc[u][v] = fmaf(a[u], bv[v], acc[u][v]);
        }
        __syncthreads();
    }

    const int lane = tid & 31;
    #pragma unroll
    for (int u = 0; u < 8; u++) {
        const int row = row0 + ty * 4 + ((u < 4) ? u : 64 + (u - 4));
        float rsum = 0.f;
        #pragma unroll
        for (int v = 0; v < 8; v++) {
            const int col = col0 + tx * 4 + ((v < 4) ? v : 64 + (v - 4));
            float e = (col <= row) ? __expf(SCALE * acc[u][v]) : 0.f;
            acc[u][v] = e;
            rsum += e;
        }
        #pragma unroll
        for (int off = 1; off < 16; off <<= 1)
            rsum += __shfl_xor_sync(0xffffffffu, rsum, off);
        if ((lane & 15) == 0)
            g_partial[((size_t)bh * LL + row) * 8 + nt] = rsum;

        float* dst = S + (size_t)row * LL + col0 + tx * 4;
        *(float4*)dst        = make_float4(acc[u][0], acc[u][1], acc[u][2], acc[u][3]);
        *(float4*)(dst + 64) = make_float4(acc[u][4], acc[u][5], acc[u][6], acc[u][7]);
    }
}

// ---------------------------------------------------------------------------
// Kernel 2: normalize series in-place (P = E / rowsum) and O = P @ V.
// grid = (pair=4, bh=64): tiles (mt, 7-mt) per CTA (balanced, 1 wave).
// NEW: software pipeline — double-buffered Ps/Vs in dynamic smem; per chunk:
// prefetch next chunk (LDG->regs), compute current buffer, then
// normalize/STG-back/STS into the other buffer; ONE sync per chunk.
// ---------------------------------------------------------------------------
// dynamic smem layout (floats):
#define AV_RINV   0
#define AV_PS     128                   // two buffers of 32*132
#define AV_PSB    4224
#define AV_VS     (128 + 2 * 4224)     // two buffers of 32*68
#define AV_VSB    2176
#define AV_SMEM_FLOATS (AV_VS + 2 * AV_VSB)   // 12928 floats
#define AV_SMEM_BYTES  (AV_SMEM_FLOATS * 4)   // 51712 B

__global__ __launch_bounds__(256, 2)
void k_av(const float* __restrict__ V, float* __restrict__ series,
          float* __restrict__ outV) {
    extern __shared__ __align__(16) float dsm[];
    const int bh = blockIdx.y;
    const int b  = bh >> 3;
    const int h  = bh & 7;
    const int tid = threadIdx.x;
    const int tx = tid & 15;
    const int ty = tid >> 4;

    float* S = series + (size_t)bh * LL * LL;
    const float* Vg = V + (size_t)b * LL * (HH * DD) + h * DD;

    const int mts[2] = { (int)blockIdx.x, 7 - (int)blockIdx.x };

    #pragma unroll 1
    for (int t = 0; t < 2; t++) {
        const int mt = mts[t];
        const int row0 = mt * 128;
        const int nchunks = 4 * (mt + 1);

        __syncthreads();   // protect smem reuse across tiles
        if (tid < 128) {
            float s = 0.f;
            for (int nt = 0; nt <= mt; nt++)
                s += g_partial[((size_t)bh * LL + row0 + tid) * 8 + nt];
            dsm[AV_RINV + tid] = 1.0f / s;
        }
        __syncthreads();

        float acc[8][4];
        #pragma unroll
        for (int u = 0; u < 8; u++)
            #pragma unroll
            for (int v = 0; v < 4; v++) acc[u][v] = 0.f;

        // per-thread prefetch registers
        float4 e[4], vv[2];
        // per-thread fixed indices
        const int ec4 = tid & 7;            // e-chunk float4 col (with it*... below)
        // chunk address helper values computed inline.

        // ---- prolog: load chunk 0, stage into buffer 0 ----
        {
            const int c = 0;
            const int nt = mt - (c >> 2);
            const int s0 = nt * 128 + (c & 3) * 32;
            #pragma unroll
            for (int it = 0; it < 4; it++) {
                int flat = it * 256 + tid;
                int c4 = flat & 7;
                int m  = flat >> 3;
                e[it] = *(const float4*)(S + (size_t)(row0 + m) * LL + s0 + c4 * 4);
            }
            #pragma unroll
            for (int it = 0; it < 2; it++) {
                int flat = it * 256 + tid;
                int sr = flat >> 4;
                int d4 = (flat & 15) << 2;
                vv[it] = *(const float4*)(Vg + (size_t)(s0 + sr) * 512 + d4);
            }
            // normalize + STG back + STS into buf 0
            float* Ps0 = dsm + AV_PS;
            float* Vs0 = dsm + AV_VS;
            #pragma unroll
            for (int it = 0; it < 4; it++) {
                int flat = it * 256 + tid;
                int c4 = flat & 7;
                int m  = flat >> 3;
                int mc = m ^ (c4 * 4);
                float r = dsm[AV_RINV + m];
                float4 v = e[it];
                v.x *= r; v.y *= r; v.z *= r; v.w *= r;
                *(float4*)(S + (size_t)(row0 + m) * LL + s0 + c4 * 4) = v;
                Ps0[(c4 * 4 + 0) * 132 + mc] = v.x;
                Ps0[(c4 * 4 + 1) * 132 + mc] = v.y;
                Ps0[(c4 * 4 + 2) * 132 + mc] = v.z;
                Ps0[(c4 * 4 + 3) * 132 + mc] = v.w;
            }
            #pragma unroll
            for (int it = 0; it < 2; it++) {
                int flat = it * 256 + tid;
                int sr = flat >> 4;
                int d4 = (flat & 15) << 2;
                *(float4*)(Vs0 + sr * 68 + d4) = vv[it];
            }
        }
        __syncthreads();

        // ---- main pipelined loop ----
        for (int c = 0; c < nchunks; c++) {
            const int buf = c & 1;
            const bool more = (c + 1 < nchunks);
            int s0n = 0;
            if (more) {
                const int cn = c + 1;
                const int ntn = mt - (cn >> 2);
                s0n = ntn * 128 + (cn & 3) * 32;
                #pragma unroll
                for (int it = 0; it < 4; it++) {
                    int flat = it * 256 + tid;
                    int c4 = flat & 7;
                    int m  = flat >> 3;
                    e[it] = *(const float4*)(S + (size_t)(row0 + m) * LL + s0n + c4 * 4);
                }
                #pragma unroll
                for (int it = 0; it < 2; it++) {
                    int flat = it * 256 + tid;
                    int sr = flat >> 4;
                    int d4 = (flat & 15) << 2;
                    vv[it] = *(const float4*)(Vg + (size_t)(s0n + sr) * 512 + d4);
                }
            }

            // compute from current buffer
            {
                const float* Ps = dsm + AV_PS + buf * AV_PSB;
                const float* Vs = dsm + AV_VS + buf * AV_VSB;
                #pragma unroll 4
                for (int k = 0; k < 32; k++) {
                    const int s4 = k & 28;
                    const int i0 = (ty * 8) ^ s4;
                    const int i1 = (ty * 8 + 4) ^ s4;
                    float a[8], bv[4];
                    *(float4*)(&a[0]) = *(const float4*)(Ps + k * 132 + i0);
                    *(float4*)(&a[4]) = *(const float4*)(Ps + k * 132 + i1);
                    *(float4*)(&bv[0]) = *(const float4*)(Vs + k * 68 + tx * 4);
                    #pragma unroll
                    for (int u = 0; u < 8; u++)
                        #pragma unroll
                        for (int v = 0; v < 4; v++)
                            acc[u][v] = fmaf(a[u], bv[v], acc[u][v]);
                }
            }

            // stage prefetched chunk into the other buffer
            if (more) {
                float* Psn = dsm + AV_PS + (buf ^ 1) * AV_PSB;
                float* Vsn = dsm + AV_VS + (buf ^ 1) * AV_VSB;
                #pragma unroll
                for (int it = 0; it < 4; it++) {
                    int flat = it * 256 + tid;
                    int c4 = flat & 7;
                    int m  = flat >> 3;
                    int mc = m ^ (c4 * 4);
                    float r = dsm[AV_RINV + m];
                    float4 v = e[it];
                    v.x *= r; v.y *= r; v.z *= r; v.w *= r;
                    *(float4*)(S + (size_t)(row0 + m) * LL + s0n + c4 * 4) = v;
                    Psn[(c4 * 4 + 0) * 132 + mc] = v.x;
                    Psn[(c4 * 4 + 1) * 132 + mc] = v.y;
                    Psn[(c4 * 4 + 2) * 132 + mc] = v.z;
                    Psn[(c4 * 4 + 3) * 132 + mc] = v.w;
                }
                #pragma unroll
                for (int it = 0; it < 2; it++) {
                    int flat = it * 256 + tid;
                    int sr = flat >> 4;
                    int d4 = (flat & 15) << 2;
                    *(float4*)(Vsn + sr * 68 + d4) = vv[it];
                }
            }
            __syncthreads();
        }

        float* Og = outV + (size_t)b * LL * (HH * DD) + h * DD;
        #pragma unroll
        for (int u = 0; u < 8; u++) {
            const int row = row0 + ty * 8 + u;
            *(float4*)(Og + (size_t)row * 512 + tx * 4) =
                make_float4(acc[u][0], acc[u][1], acc[u][2], acc[u][3]);
        }
    }
}

// ---------------------------------------------------------------------------
// Kernel 3: prior association (MUFU-bound, ~20us; unchanged).
// ---------------------------------------------------------------------------
__global__ __launch_bounds__(256)
void k_prior(const float* __restrict__ sigma, float* __restrict__ prior) {
    const int b  = blockIdx.y;
    const int i0 = blockIdx.x * 32;
    const int tid = threadIdx.x;

    __shared__ float rl[8][1024];
    __shared__ float red[8];

    for (int idx = tid; idx < 8 * 1024; idx += 256) {
        int h = idx >> 10;
        int s = idx & 1023;
        rl[h][s] = -1.0f / sigma[((size_t)b * 8 + h) * 1024 + s];
    }
    __syncthreads();

    const int lane = tid & 31, wid = tid >> 5;

    for (int ii = 0; ii < 32; ii++) {
        const int i = i0 + ii;
        float p[4];
        float sum = 0.f;
        #pragma unroll
        for (int j = 0; j < 4; j++) {
            const int s = tid + j * 256;
            const float d = (float)((i > s) ? (i - s) : (s - i));
            float a = 0.f;
            #pragma unroll
            for (int h = 0; h < 8; h++)
                a += __expf(d * rl[h][s]);
            p[j] = a;
            sum += a;
        }
        #pragma unroll
        for (int off = 16; off; off >>= 1)
            sum += __shfl_xor_sync(0xffffffffu, sum, off);
        if (lane == 0) red[wid] = sum;
        __syncthreads();
        float tot = 0.f;
        #pragma unroll
        for (int w = 0; w < 8; w++) tot += red[w];
        const float inv = 1.0f / tot;
        float* dst = prior + (size_t)(b * 1024 + i) * 1024;
        #pragma unroll
        for (int j = 0; j < 4; j++)
            dst[tid + j * 256] = p[j] * inv;
        __syncthreads();
    }
}

// ---------------------------------------------------------------------------
extern "C" void kernel_launch(void* const* d_in, const int* in_sizes, int n_in,
                              void* d_out, int out_size) {
    (void)in_sizes; (void)n_in; (void)out_size;
    const float* Q   = (const float*)d_in[0];
    const float* K   = (const float*)d_in[1];
    const float* V   = (const float*)d_in[2];
    const float* sig = (const float*)d_in[3];
    float* out    = (float*)d_out;
    float* outV   = out;                 // (B,L,H,D)
    float* series = out + OFF_SERIES;    // (B,H,L,S)
    float* prior  = out + OFF_PRIOR;     // (B,L,S)

    // host-side, idempotent, capture-legal (not a stream op, no allocation)
    cudaFuncSetAttribute(k_av, cudaFuncAttributeMaxDynamicSharedMemorySize,
                         AV_SMEM_BYTES);

    k_scores<<<dim3(8, 8, Bb * HH), 256>>>(Q, K, series);
    k_av    <<<dim3(4, Bb * HH),   256, AV_SMEM_BYTES>>>(V, series, outV);
    k_prior <<<dim3(32, Bb),       256>>>(sig, prior);
}

// round 9
// speedup vs baseline: 1.9010x; 1.1529x over previous
#include <cuda_runtime.h>
#include <cuda_bf16.h>
#include <cuda_fp16.h>
#include <cstdint>

// Problem constants
#define Bb 8
#define LL 1024
#define HH 8
#define EE 64
#define DD 64
#define SCALE 0.125f   // 1/sqrt(64)

// Output layout (concatenated flattened tuple):
//   V:      (B,L,H,D)   at 0              size 4,194,304
//   series: (B,H,L,S)   at 4,194,304      size 67,108,864
//   prior:  (B,L,S)     at 71,303,168     size 8,388,608
#define OFF_SERIES 4194304
#define OFF_PRIOR  71303168

// Scratch: per-(b,h,row,ntile) partial row sums of unnormalized exp scores.
__device__ float g_partial[Bb * HH * LL * 8];  // 2 MB

// ---------------- warp-MMA helpers (sm_80-era PTX, sm_103-portable) --------
struct U4 { uint32_t x, y, z, w; };

__device__ __forceinline__ U4 ldmx4(uint32_t a) {
    U4 r;
    asm volatile("ldmatrix.sync.aligned.m8n8.x4.shared.b16 {%0,%1,%2,%3}, [%4];"
                 : "=r"(r.x), "=r"(r.y), "=r"(r.z), "=r"(r.w) : "r"(a));
    return r;
}
__device__ __forceinline__ void mma16816(float* c, const U4& a,
                                         uint32_t b0, uint32_t b1) {
    asm volatile("mma.sync.aligned.m16n8k16.row.col.f32.f16.f16.f32 "
                 "{%0,%1,%2,%3}, {%4,%5,%6,%7}, {%8,%9}, {%0,%1,%2,%3};"
                 : "+f"(c[0]), "+f"(c[1]), "+f"(c[2]), "+f"(c[3])
                 : "r"(a.x), "r"(a.y), "r"(a.z), "r"(a.w), "r"(b0), "r"(b1));
}
__device__ __forceinline__ uint32_t pack2h(half a, half b) {
    return (uint32_t)__half_as_ushort(a) | ((uint32_t)__half_as_ushort(b) << 16);
}
__device__ __forceinline__ uint32_t smem_u32(const void* p) {
    uint32_t a;
    asm("{ .reg .u64 t; cvta.to.shared.u64 t, %1; cvt.u32.u64 %0, t; }"
        : "=r"(a) : "l"(p));
    return a;
}
// SW128 swizzle (Swizzle<3,4,3>) on byte offsets within a 128B-row tile
__device__ __forceinline__ uint32_t sw128(uint32_t off) {
    return off ^ ((off >> 3) & 0x70);
}

// k_scores dynamic smem layout (bytes): 4 fp16 tiles 128x64 (16KB each),
// epilogue overlays a float[128][132] staging buffer (67584 B total).
#define SMQ_H 0
#define SMQ_L 16384
#define SMK_H 32768
#define SMK_L 49152
#define KS_SMEM 67584

// ---------------------------------------------------------------------------
// Kernel 1 (HMMA): E = exp(scale * Q K^T) for causal tiles.
// grid = (nt=8, mt=8, bh=64), block 256 (2x4 warps), tile 128x128,
// warp tile 64x32, fp16 hi/lo split (3 mma terms), fp32 accum.
// ---------------------------------------------------------------------------
__global__ __launch_bounds__(256, 2)
void k_scores(const float* __restrict__ Q, const float* __restrict__ K,
              float* __restrict__ series) {
    extern __shared__ __align__(1024) char dsm[];
    const int nt = blockIdx.x;
    const int mt = blockIdx.y;
    const int bh = blockIdx.z;          // b*8 + h
    const int b  = bh >> 3;
    const int h  = bh & 7;
    const int tid = threadIdx.x;

    float* S = series + (size_t)bh * LL * LL;
    const int row0 = mt * 128, col0 = nt * 128;

    if (nt > mt) {
        const float4 z = make_float4(0.f, 0.f, 0.f, 0.f);
        #pragma unroll
        for (int i = 0; i < 16; i++) {
            int flat = i * 256 + tid;
            int r = flat >> 5;
            int c = (flat & 31) << 2;
            *(float4*)(S + (size_t)(row0 + r) * LL + col0 + c) = z;
        }
        return;
    }

    __shared__ float rs[128][4];   // per-(row, warp_n) partial sums

    const uint32_t smb = smem_u32(dsm);
    const int wid = tid >> 5, lane = tid & 31;
    const int warp_m = wid & 1, warp_n = wid >> 1;
    const int m0 = warp_m * 64, n0w = warp_n * 32;
    const int g = lane >> 2, t = lane & 3;

    // ---- stage Q,K as fp16 hi/lo, SW128 swizzled (coalesced LDG) ----
    const float* Qg = Q + (size_t)b * LL * (HH * EE) + h * EE;  // + l*512 + e
    const float* Kg = K + (size_t)b * LL * (HH * EE) + h * EE;
    #pragma unroll
    for (int it = 0; it < 8; it++) {
        int flat = it * 256 + tid;      // 2048 float4 per matrix
        int c4 = flat & 15;
        int r  = flat >> 4;
        uint32_t so = sw128((uint32_t)(r * 128 + c4 * 8));

        float4 v = *(const float4*)(Qg + (size_t)(row0 + r) * 512 + c4 * 4);
        half hx = __float2half_rn(v.x), hy = __float2half_rn(v.y);
        half hz = __float2half_rn(v.z), hw = __float2half_rn(v.w);
        *(uint2*)(dsm + SMQ_H + so) = make_uint2(pack2h(hx, hy), pack2h(hz, hw));
        *(uint2*)(dsm + SMQ_L + so) = make_uint2(
            pack2h(__float2half_rn(v.x - __half2float(hx)),
                   __float2half_rn(v.y - __half2float(hy))),
            pack2h(__float2half_rn(v.z - __half2float(hz)),
                   __float2half_rn(v.w - __half2float(hw))));

        float4 w = *(const float4*)(Kg + (size_t)(col0 + r) * 512 + c4 * 4);
        half kx = __float2half_rn(w.x), ky = __float2half_rn(w.y);
        half kz = __float2half_rn(w.z), kw = __float2half_rn(w.w);
        *(uint2*)(dsm + SMK_H + so) = make_uint2(pack2h(kx, ky), pack2h(kz, kw));
        *(uint2*)(dsm + SMK_L + so) = make_uint2(
            pack2h(__float2half_rn(w.x - __half2float(kx)),
                   __float2half_rn(w.y - __half2float(ky))),
            pack2h(__float2half_rn(w.z - __half2float(kz)),
                   __float2half_rn(w.w - __half2float(kw))));
    }
    __syncthreads();

    // ---- ldmatrix address components ----
    // A x4: lanes 0-7 rows+0 @e0 | 8-15 rows+8 @e0 | 16-23 rows+0 @e8 | 24-31 rows+8 @e8
    const int a_row = (lane & 7) + ((lane >> 3) & 1) * 8;
    const int a_c16 = (lane >> 4) & 1;
    // B x4: lanes 0-7 n+0 @e0 | 8-15 n+0 @e8 | 16-23 n+8 @e0 | 24-31 n+8 @e8
    const int b_row = (lane & 7) + ((lane >> 4) & 1) * 8;
    const int b_c16 = (lane >> 3) & 1;

    uint32_t offA[4], offB[2];
    #pragma unroll
    for (int im = 0; im < 4; im++)
        offA[im] = (uint32_t)((m0 + im * 16 + a_row) * 128 + a_c16 * 16);
    #pragma unroll
    for (int hb = 0; hb < 2; hb++)
        offB[hb] = (uint32_t)((n0w + hb * 16 + b_row) * 128 + b_c16 * 16);

    float c[4][4][4];
    #pragma unroll
    for (int im = 0; im < 4; im++)
        #pragma unroll
        for (int in = 0; in < 4; in++)
            #pragma unroll
            for (int q = 0; q < 4; q++) c[im][in][q] = 0.f;

    // ---- mainloop: 4 k-steps x (AhBh + AhBl + AlBh) ----
    #pragma unroll
    for (int ks = 0; ks < 4; ks++) {
        const uint32_t ko = ks * 32;
        U4 A[4], Bh[2], Bl[2];
        #pragma unroll
        for (int hb = 0; hb < 2; hb++)
            Bh[hb] = ldmx4(smb + SMK_H + sw128(offB[hb] + ko));
        #pragma unroll
        for (int im = 0; im < 4; im++)
            A[im] = ldmx4(smb + SMQ_H + sw128(offA[im] + ko));
        #pragma unroll
        for (int im = 0; im < 4; im++) {
            mma16816(c[im][0], A[im], Bh[0].x, Bh[0].y);
            mma16816(c[im][1], A[im], Bh[0].z, Bh[0].w);
            mma16816(c[im][2], A[im], Bh[1].x, Bh[1].y);
            mma16816(c[im][3], A[im], Bh[1].z, Bh[1].w);
        }
        #pragma unroll
        for (int hb = 0; hb < 2; hb++)
            Bl[hb] = ldmx4(smb + SMK_L + sw128(offB[hb] + ko));
        #pragma unroll
        for (int im = 0; im < 4; im++) {
            mma16816(c[im][0], A[im], Bl[0].x, Bl[0].y);
            mma16816(c[im][1], A[im], Bl[0].z, Bl[0].w);
            mma16816(c[im][2], A[im], Bl[1].x, Bl[1].y);
            mma16816(c[im][3], A[im], Bl[1].z, Bl[1].w);
        }
        #pragma unroll
        for (int im = 0; im < 4; im++)
            A[im] = ldmx4(smb + SMQ_L + sw128(offA[im] + ko));
        #pragma unroll
        for (int im = 0; im < 4; im++) {
            mma16816(c[im][0], A[im], Bh[0].x, Bh[0].y);
            mma16816(c[im][1], A[im], Bh[0].z, Bh[0].w);
            mma16816(c[im][2], A[im], Bh[1].x, Bh[1].y);
            mma16816(c[im][3], A[im], Bh[1].z, Bh[1].w);
        }
    }
    __syncthreads();   // all ldmatrix done; safe to overlay Ds on input tiles

    // ---- epilogue: mask + exp in regs, rowsums, stage to smem ----
    float* Ds = (float*)dsm;   // [128][132]
    #pragma unroll
    for (int im = 0; im < 4; im++) {
        const int lrA = m0 + im * 16 + g;
        const int lrB = lrA + 8;
        const int rowA = row0 + lrA, rowB = row0 + lrB;
        float sA = 0.f, sB = 0.f;
        #pragma unroll
        for (int in = 0; in < 4; in++) {
            const int cb = n0w + in * 8 + 2 * t;
            const int colX = col0 + cb, colY = colX + 1;
            float e0 = (colX <= rowA) ? __expf(SCALE * c[im][in][0]) : 0.f;
            float e1 = (colY <= rowA) ? __expf(SCALE * c[im][in][1]) : 0.f;
            float e2 = (colX <= rowB) ? __expf(SCALE * c[im][in][2]) : 0.f;
            float e3 = (colY <= rowB) ? __expf(SCALE * c[im][in][3]) : 0.f;
            sA += e0 + e1; sB += e2 + e3;
            *(float2*)(Ds + lrA * 132 + cb) = make_float2(e0, e1);
            *(float2*)(Ds + lrB * 132 + cb) = make_float2(e2, e3);
        }
        sA += __shfl_xor_sync(0xffffffffu, sA, 1);
        sA += __shfl_xor_sync(0xffffffffu, sA, 2);
        sB += __shfl_xor_sync(0xffffffffu, sB, 1);
        sB += __shfl_xor_sync(0xffffffffu, sB, 2);
        if (t == 0) { rs[lrA][warp_n] = sA; rs[lrB][warp_n] = sB; }
    }
    __syncthreads();

    if (tid < 128)
        g_partial[((size_t)bh * LL + row0 + tid) * 8 + nt] =
            rs[tid][0] + rs[tid][1] + rs[tid][2] + rs[tid][3];

    // ---- coalesced tile store ----
    #pragma unroll
    for (int it = 0; it < 16; it++) {
        int flat = it * 256 + tid;      // 4096 float4
        int c4 = flat & 31;
        int r  = flat >> 5;
        float4 v = *(const float4*)(Ds + r * 132 + c4 * 4);
        *(float4*)(S + (size_t)(row0 + r) * LL + col0 + c4 * 4) = v;
    }
}

// ---------------------------------------------------------------------------
// Kernel 2: normalize series in-place (P = E / rowsum) and O = P @ V.
// grid = (pair=4, bh=64); software-pipelined double buffers (R8, unchanged).
// ---------------------------------------------------------------------------
#define AV_RINV   0
#define AV_PS     128
#define AV_PSB    4224
#define AV_VS     (128 + 2 * 4224)
#define AV_VSB    2176
#define AV_SMEM_FLOATS (AV_VS + 2 * AV_VSB)
#define AV_SMEM_BYTES  (AV_SMEM_FLOATS * 4)

__global__ __launch_bounds__(256, 2)
void k_av(const float* __restrict__ V, float* __restrict__ series,
          float* __restrict__ outV) {
    extern __shared__ __align__(16) float dsmf[];
    const int bh = blockIdx.y;
    const int b  = bh >> 3;
    const int h  = bh & 7;
    const int tid = threadIdx.x;
    const int tx = tid & 15;
    const int ty = tid >> 4;

    float* S = series + (size_t)bh * LL * LL;
    const float* Vg = V + (size_t)b * LL * (HH * DD) + h * DD;

    const int mts[2] = { (int)blockIdx.x, 7 - (int)blockIdx.x };

    #pragma unroll 1
    for (int t = 0; t < 2; t++) {
        const int mt = mts[t];
        const int row0 = mt * 128;
        const int nchunks = 4 * (mt + 1);

        __syncthreads();
        if (tid < 128) {
            float s = 0.f;
            for (int nt = 0; nt <= mt; nt++)
                s += g_partial[((size_t)bh * LL + row0 + tid) * 8 + nt];
            dsmf[AV_RINV + tid] = 1.0f / s;
        }
        __syncthreads();

        float acc[8][4];
        #pragma unroll
        for (int u = 0; u < 8; u++)
            #pragma unroll
            for (int v = 0; v < 4; v++) acc[u][v] = 0.f;

        float4 e[4], vv[2];

        {   // prolog: chunk 0 -> buffer 0
            const int s0 = mt * 128;
            #pragma unroll
            for (int it = 0; it < 4; it++) {
                int flat = it * 256 + tid;
                int c4 = flat & 7;
                int m  = flat >> 3;
                e[it] = *(const float4*)(S + (size_t)(row0 + m) * LL + s0 + c4 * 4);
            }
            #pragma unroll
            for (int it = 0; it < 2; it++) {
                int flat = it * 256 + tid;
                int sr = flat >> 4;
                int d4 = (flat & 15) << 2;
                vv[it] = *(const float4*)(Vg + (size_t)(s0 + sr) * 512 + d4);
            }
            float* Ps0 = dsmf + AV_PS;
            float* Vs0 = dsmf + AV_VS;
            #pragma unroll
            for (int it = 0; it < 4; it++) {
                int flat = it * 256 + tid;
                int c4 = flat & 7;
                int m  = flat >> 3;
                int mc = m ^ (c4 * 4);
                float r = dsmf[AV_RINV + m];
                float4 v = e[it];
                v.x *= r; v.y *= r; v.z *= r; v.w *= r;
                *(float4*)(S + (size_t)(row0 + m) * LL + s0 + c4 * 4) = v;
                Ps0[(c4 * 4 + 0) * 132 + mc] = v.x;
                Ps0[(c4 * 4 + 1) * 132 + mc] = v.y;
                Ps0[(c4 * 4 + 2) * 132 + mc] = v.z;
                Ps0[(c4 * 4 + 3) * 132 + mc] = v.w;
            }
            #pragma unroll
            for (int it = 0; it < 2; it++) {
                int flat = it * 256 + tid;
                int sr = flat >> 4;
                int d4 = (flat & 15) << 2;
                *(float4*)(Vs0 + sr * 68 + d4) = vv[it];
            }
        }
        __syncthreads();

        for (int cc = 0; cc < nchunks; cc++) {
            const int buf = cc & 1;
            const bool more = (cc + 1 < nchunks);
            int s0n = 0;
            if (more) {
                const int cn = cc + 1;
                const int ntn = mt - (cn >> 2);
                s0n = ntn * 128 + (cn & 3) * 32;
                #pragma unroll
                for (int it = 0; it < 4; it++) {
                    int flat = it * 256 + tid;
                    int c4 = flat & 7;
                    int m  = flat >> 3;
                    e[it] = *(const float4*)(S + (size_t)(row0 + m) * LL + s0n + c4 * 4);
                }
                #pragma unroll
                for (int it = 0; it < 2; it++) {
                    int flat = it * 256 + tid;
                    int sr = flat >> 4;
                    int d4 = (flat & 15) << 2;
                    vv[it] = *(const float4*)(Vg + (size_t)(s0n + sr) * 512 + d4);
                }
            }

            {
                const float* Ps = dsmf + AV_PS + buf * AV_PSB;
                const float* Vs = dsmf + AV_VS + buf * AV_VSB;
                #pragma unroll 4
                for (int k = 0; k < 32; k++) {
                    const int s4 = k & 28;
                    const int i0 = (ty * 8) ^ s4;
                    const int i1 = (ty * 8 + 4) ^ s4;
                    float a[8], bv[4];
                    *(float4*)(&a[0]) = *(const float4*)(Ps + k * 132 + i0);
                    *(float4*)(&a[4]) = *(const float4*)(Ps + k * 132 + i1);
                    *(float4*)(&bv[0]) = *(const float4*)(Vs + k * 68 + tx * 4);
                    #pragma unroll
                    for (int u = 0; u < 8; u++)
                        #pragma unroll
                        for (int v = 0; v < 4; v++)
                            acc[u][v] = fmaf(a[u], bv[v], acc[u][v]);
                }
            }

            if (more) {
                float* Psn = dsmf + AV_PS + (buf ^ 1) * AV_PSB;
                float* Vsn = dsmf + AV_VS + (buf ^ 1) * AV_VSB;
                #pragma unroll
                for (int it = 0; it < 4; it++) {
                    int flat = it * 256 + tid;
                    int c4 = flat & 7;
                    int m  = flat >> 3;
                    int mc = m ^ (c4 * 4);
                    float r = dsmf[AV_RINV + m];
                    float4 v = e[it];
                    v.x *= r; v.y *= r; v.z *= r; v.w *= r;
                    *(float4*)(S + (size_t)(row0 + m) * LL + s0n + c4 * 4) = v;
                    Psn[(c4 * 4 + 0) * 132 + mc] = v.x;
                    Psn[(c4 * 4 + 1) * 132 + mc] = v.y;
                    Psn[(c4 * 4 + 2) * 132 + mc] = v.z;
                    Psn[(c4 * 4 + 3) * 132 + mc] = v.w;
                }
                #pragma unroll
                for (int it = 0; it < 2; it++) {
                    int flat = it * 256 + tid;
                    int sr = flat >> 4;
                    int d4 = (flat & 15) << 2;
                    *(float4*)(Vsn + sr * 68 + d4) = vv[it];
                }
            }
            __syncthreads();
        }

        float* Og = outV + (size_t)b * LL * (HH * DD) + h * DD;
        #pragma unroll
        for (int u = 0; u < 8; u++) {
            const int row = row0 + ty * 8 + u;
            *(float4*)(Og + (size_t)row * 512 + tx * 4) =
                make_float4(acc[u][0], acc[u][1], acc[u][2], acc[u][3]);
        }
    }
}

// ---------------------------------------------------------------------------
// Kernel 3: prior association (MUFU-bound, ~20us; unchanged).
// ---------------------------------------------------------------------------
__global__ __launch_bounds__(256)
void k_prior(const float* __restrict__ sigma, float* __restrict__ prior) {
    const int b  = blockIdx.y;
    const int i0 = blockIdx.x * 32;
    const int tid = threadIdx.x;

    __shared__ float rl[8][1024];
    __shared__ float red[8];

    for (int idx = tid; idx < 8 * 1024; idx += 256) {
        int h = idx >> 10;
        int s = idx & 1023;
        rl[h][s] = -1.0f / sigma[((size_t)b * 8 + h) * 1024 + s];
    }
    __syncthreads();

    const int lane = tid & 31, wid = tid >> 5;

    for (int ii = 0; ii < 32; ii++) {
        const int i = i0 + ii;
        float p[4];
        float sum = 0.f;
        #pragma unroll
        for (int j = 0; j < 4; j++) {
            const int s = tid + j * 256;
            const float d = (float)((i > s) ? (i - s) : (s - i));
            float a = 0.f;
            #pragma unroll
            for (int h = 0; h < 8; h++)
                a += __expf(d * rl[h][s]);
            p[j] = a;
            sum += a;
        }
        #pragma unroll
        for (int off = 16; off; off >>= 1)
            sum += __shfl_xor_sync(0xffffffffu, sum, off);
        if (lane == 0) red[wid] = sum;
        __syncthreads();
        float tot = 0.f;
        #pragma unroll
        for (int w = 0; w < 8; w++) tot += red[w];
        const float inv = 1.0f / tot;
        float* dst = prior + (size_t)(b * 1024 + i) * 1024;
        #pragma unroll
        for (int j = 0; j < 4; j++)
            dst[tid + j * 256] = p[j] * inv;
        __syncthreads();
    }
}

// ---------------------------------------------------------------------------
extern "C" void kernel_launch(void* const* d_in, const int* in_sizes, int n_in,
                              void* d_out, int out_size) {
    (void)in_sizes; (void)n_in; (void)out_size;
    const float* Q   = (const float*)d_in[0];
    const float* K   = (const float*)d_in[1];
    const float* V   = (const float*)d_in[2];
    const float* sig = (const float*)d_in[3];
    float* out    = (float*)d_out;
    float* outV   = out;                 // (B,L,H,D)
    float* series = out + OFF_SERIES;    // (B,H,L,S)
    float* prior  = out + OFF_PRIOR;     // (B,L,S)

    cudaFuncSetAttribute(k_scores, cudaFuncAttributeMaxDynamicSharedMemorySize,
                         KS_SMEM);
    cudaFuncSetAttribute(k_av, cudaFuncAttributeMaxDynamicSharedMemorySize,
                         AV_SMEM_BYTES);

    k_scores<<<dim3(8, 8, Bb * HH), 256, KS_SMEM>>>(Q, K, series);
    k_av    <<<dim3(4, Bb * HH),   256, AV_SMEM_BYTES>>>(V, series, outV);
    k_prior <<<dim3(32, Bb),       256>>>(sig, prior);
}

// round 10
// speedup vs baseline: 2.6078x; 1.3718x over previous
#include <cuda_runtime.h>
#include <cuda_bf16.h>
#include <cuda_fp16.h>
#include <cstdint>

// Problem constants
#define Bb 8
#define LL 1024
#define HH 8
#define EE 64
#define DD 64
#define SCALE 0.125f   // 1/sqrt(64)

// Output layout (concatenated flattened tuple):
//   V:      (B,L,H,D)   at 0              size 4,194,304
//   series: (B,H,L,S)   at 4,194,304      size 67,108,864
//   prior:  (B,L,S)     at 71,303,168     size 8,388,608
#define OFF_SERIES 4194304
#define OFF_PRIOR  71303168

// Scratch: per-(b,h,row,ntile) partial row sums of unnormalized exp scores.
__device__ float g_partial[Bb * HH * LL * 8];  // 2 MB

// ---------------- warp-MMA helpers (sm_80-era PTX, sm_103-portable) --------
struct U4 { uint32_t x, y, z, w; };

__device__ __forceinline__ U4 ldmx4(uint32_t a) {
    U4 r;
    asm volatile("ldmatrix.sync.aligned.m8n8.x4.shared.b16 {%0,%1,%2,%3}, [%4];"
                 : "=r"(r.x), "=r"(r.y), "=r"(r.z), "=r"(r.w) : "r"(a));
    return r;
}
__device__ __forceinline__ U4 ldmx4t(uint32_t a) {
    U4 r;
    asm volatile("ldmatrix.sync.aligned.m8n8.x4.trans.shared.b16 {%0,%1,%2,%3}, [%4];"
                 : "=r"(r.x), "=r"(r.y), "=r"(r.z), "=r"(r.w) : "r"(a));
    return r;
}
__device__ __forceinline__ void mma16816(float* c, const U4& a,
                                         uint32_t b0, uint32_t b1) {
    asm volatile("mma.sync.aligned.m16n8k16.row.col.f32.f16.f16.f32 "
                 "{%0,%1,%2,%3}, {%4,%5,%6,%7}, {%8,%9}, {%0,%1,%2,%3};"
                 : "+f"(c[0]), "+f"(c[1]), "+f"(c[2]), "+f"(c[3])
                 : "r"(a.x), "r"(a.y), "r"(a.z), "r"(a.w), "r"(b0), "r"(b1));
}
__device__ __forceinline__ uint32_t pack2h(half a, half b) {
    return (uint32_t)__half_as_ushort(a) | ((uint32_t)__half_as_ushort(b) << 16);
}
__device__ __forceinline__ uint32_t smem_u32(const void* p) {
    uint32_t a;
    asm("{ .reg .u64 t; cvta.to.shared.u64 t, %1; cvt.u32.u64 %0, t; }"
        : "=r"(a) : "l"(p));
    return a;
}
// SW128 swizzle (Swizzle<3,4,3>) on byte offsets within a 128B-row tile
__device__ __forceinline__ uint32_t sw128(uint32_t off) {
    return off ^ ((off >> 3) & 0x70);
}

// ===========================================================================
// Kernel 1 (HMMA): E = exp(scale * Q K^T) for causal tiles. (R9, unchanged)
// ===========================================================================
#define SMQ_H 0
#define SMQ_L 16384
#define SMK_H 32768
#define SMK_L 49152
#define KS_SMEM 67584

__global__ __launch_bounds__(256, 2)
void k_scores(const float* __restrict__ Q, const float* __restrict__ K,
              float* __restrict__ series) {
    extern __shared__ __align__(1024) char dsm[];
    const int nt = blockIdx.x;
    const int mt = blockIdx.y;
    const int bh = blockIdx.z;          // b*8 + h
    const int b  = bh >> 3;
    const int h  = bh & 7;
    const int tid = threadIdx.x;

    float* S = series + (size_t)bh * LL * LL;
    const int row0 = mt * 128, col0 = nt * 128;

    if (nt > mt) {
        const float4 z = make_float4(0.f, 0.f, 0.f, 0.f);
        #pragma unroll
        for (int i = 0; i < 16; i++) {
            int flat = i * 256 + tid;
            int r = flat >> 5;
            int c = (flat & 31) << 2;
            *(float4*)(S + (size_t)(row0 + r) * LL + col0 + c) = z;
        }
        return;
    }

    __shared__ float rs[128][4];   // per-(row, warp_n) partial sums

    const uint32_t smb = smem_u32(dsm);
    const int wid = tid >> 5, lane = tid & 31;
    const int warp_m = wid & 1, warp_n = wid >> 1;
    const int m0 = warp_m * 64, n0w = warp_n * 32;
    const int g = lane >> 2, t = lane & 3;

    const float* Qg = Q + (size_t)b * LL * (HH * EE) + h * EE;  // + l*512 + e
    const float* Kg = K + (size_t)b * LL * (HH * EE) + h * EE;
    #pragma unroll
    for (int it = 0; it < 8; it++) {
        int flat = it * 256 + tid;      // 2048 float4 per matrix
        int c4 = flat & 15;
        int r  = flat >> 4;
        uint32_t so = sw128((uint32_t)(r * 128 + c4 * 8));

        float4 v = *(const float4*)(Qg + (size_t)(row0 + r) * 512 + c4 * 4);
        half hx = __float2half_rn(v.x), hy = __float2half_rn(v.y);
        half hz = __float2half_rn(v.z), hw = __float2half_rn(v.w);
        *(uint2*)(dsm + SMQ_H + so) = make_uint2(pack2h(hx, hy), pack2h(hz, hw));
        *(uint2*)(dsm + SMQ_L + so) = make_uint2(
            pack2h(__float2half_rn(v.x - __half2float(hx)),
                   __float2half_rn(v.y - __half2float(hy))),
            pack2h(__float2half_rn(v.z - __half2float(hz)),
                   __float2half_rn(v.w - __half2float(hw))));

        float4 w = *(const float4*)(Kg + (size_t)(col0 + r) * 512 + c4 * 4);
        half kx = __float2half_rn(w.x), ky = __float2half_rn(w.y);
        half kz = __float2half_rn(w.z), kw = __float2half_rn(w.w);
        *(uint2*)(dsm + SMK_H + so) = make_uint2(pack2h(kx, ky), pack2h(kz, kw));
        *(uint2*)(dsm + SMK_L + so) = make_uint2(
            pack2h(__float2half_rn(w.x - __half2float(kx)),
                   __float2half_rn(w.y - __half2float(ky))),
            pack2h(__float2half_rn(w.z - __half2float(kz)),
                   __float2half_rn(w.w - __half2float(kw))));
    }
    __syncthreads();

    const int a_row = (lane & 7) + ((lane >> 3) & 1) * 8;
    const int a_c16 = (lane >> 4) & 1;
    const int b_row = (lane & 7) + ((lane >> 4) & 1) * 8;
    const int b_c16 = (lane >> 3) & 1;

    uint32_t offA[4], offB[2];
    #pragma unroll
    for (int im = 0; im < 4; im++)
        offA[im] = (uint32_t)((m0 + im * 16 + a_row) * 128 + a_c16 * 16);
    #pragma unroll
    for (int hb = 0; hb < 2; hb++)
        offB[hb] = (uint32_t)((n0w + hb * 16 + b_row) * 128 + b_c16 * 16);

    float c[4][4][4];
    #pragma unroll
    for (int im = 0; im < 4; im++)
        #pragma unroll
        for (int in = 0; in < 4; in++)
            #pragma unroll
            for (int q = 0; q < 4; q++) c[im][in][q] = 0.f;

    #pragma unroll
    for (int ks = 0; ks < 4; ks++) {
        const uint32_t ko = ks * 32;
        U4 A[4], Bh[2], Bl[2];
        #pragma unroll
        for (int hb = 0; hb < 2; hb++)
            Bh[hb] = ldmx4(smb + SMK_H + sw128(offB[hb] + ko));
        #pragma unroll
        for (int im = 0; im < 4; im++)
            A[im] = ldmx4(smb + SMQ_H + sw128(offA[im] + ko));
        #pragma unroll
        for (int im = 0; im < 4; im++) {
            mma16816(c[im][0], A[im], Bh[0].x, Bh[0].y);
            mma16816(c[im][1], A[im], Bh[0].z, Bh[0].w);
            mma16816(c[im][2], A[im], Bh[1].x, Bh[1].y);
            mma16816(c[im][3], A[im], Bh[1].z, Bh[1].w);
        }
        #pragma unroll
        for (int hb = 0; hb < 2; hb++)
            Bl[hb] = ldmx4(smb + SMK_L + sw128(offB[hb] + ko));
        #pragma unroll
        for (int im = 0; im < 4; im++) {
            mma16816(c[im][0], A[im], Bl[0].x, Bl[0].y);
            mma16816(c[im][1], A[im], Bl[0].z, Bl[0].w);
            mma16816(c[im][2], A[im], Bl[1].x, Bl[1].y);
            mma16816(c[im][3], A[im], Bl[1].z, Bl[1].w);
        }
        #pragma unroll
        for (int im = 0; im < 4; im++)
            A[im] = ldmx4(smb + SMQ_L + sw128(offA[im] + ko));
        #pragma unroll
        for (int im = 0; im < 4; im++) {
            mma16816(c[im][0], A[im], Bh[0].x, Bh[0].y);
            mma16816(c[im][1], A[im], Bh[0].z, Bh[0].w);
            mma16816(c[im][2], A[im], Bh[1].x, Bh[1].y);
            mma16816(c[im][3], A[im], Bh[1].z, Bh[1].w);
        }
    }
    __syncthreads();   // safe to overlay Ds on input tiles

    float* Ds = (float*)dsm;   // [128][132]
    #pragma unroll
    for (int im = 0; im < 4; im++) {
        const int lrA = m0 + im * 16 + g;
        const int lrB = lrA + 8;
        const int rowA = row0 + lrA, rowB = row0 + lrB;
        float sA = 0.f, sB = 0.f;
        #pragma unroll
        for (int in = 0; in < 4; in++) {
            const int cb = n0w + in * 8 + 2 * t;
            const int colX = col0 + cb, colY = colX + 1;
            float e0 = (colX <= rowA) ? __expf(SCALE * c[im][in][0]) : 0.f;
            float e1 = (colY <= rowA) ? __expf(SCALE * c[im][in][1]) : 0.f;
            float e2 = (colX <= rowB) ? __expf(SCALE * c[im][in][2]) : 0.f;
            float e3 = (colY <= rowB) ? __expf(SCALE * c[im][in][3]) : 0.f;
            sA += e0 + e1; sB += e2 + e3;
            *(float2*)(Ds + lrA * 132 + cb) = make_float2(e0, e1);
            *(float2*)(Ds + lrB * 132 + cb) = make_float2(e2, e3);
        }
        sA += __shfl_xor_sync(0xffffffffu, sA, 1);
        sA += __shfl_xor_sync(0xffffffffu, sA, 2);
        sB += __shfl_xor_sync(0xffffffffu, sB, 1);
        sB += __shfl_xor_sync(0xffffffffu, sB, 2);
        if (t == 0) { rs[lrA][warp_n] = sA; rs[lrB][warp_n] = sB; }
    }
    __syncthreads();

    if (tid < 128)
        g_partial[((size_t)bh * LL + row0 + tid) * 8 + nt] =
            rs[tid][0] + rs[tid][1] + rs[tid][2] + rs[tid][3];

    #pragma unroll
    for (int it = 0; it < 16; it++) {
        int flat = it * 256 + tid;      // 4096 float4
        int c4 = flat & 31;
        int r  = flat >> 5;
        float4 v = *(const float4*)(Ds + r * 132 + c4 * 4);
        *(float4*)(S + (size_t)(row0 + r) * LL + col0 + c4 * 4) = v;
    }
}

// ===========================================================================
// Kernel 2 (HMMA): normalize series in-place (P = E/rowsum) and O = P @ V.
// grid = (pair=4, bh=64): tiles (mt, 7-mt) per CTA; s-chunks of 64;
// double-buffered fp16 hi/lo staging; reg-prefetch pipeline, 1 sync/chunk.
// ===========================================================================
// dyn smem (bytes): rinv 512 @0; two buffers @1024 + b*49152:
//   Ph 16384 | Pl 16384 | Vh 8192 | Vl 8192
#define AV_BUF0   1024
#define AV_BUFSZ  49152
#define AV_PHO    0
#define AV_PLO    16384
#define AV_VHO    32768
#define AV_VLO    40960
#define AV_SMEM   (1024 + 2 * 49152)   // 99328 B

__device__ __forceinline__ void av_stage(
    const float4* e, const float4* vv, float* __restrict__ S,
    const float* __restrict__ rinv, char* __restrict__ buf,
    int row0, int s0, int tid) {
    char* Ph = buf + AV_PHO;
    char* Pl = buf + AV_PLO;
    char* Vh = buf + AV_VHO;
    char* Vl = buf + AV_VLO;
    #pragma unroll
    for (int it = 0; it < 8; it++) {
        int flat = it * 256 + tid;      // 2048 float4 = 128 x 16
        int c4 = flat & 15;
        int m  = flat >> 4;
        float r = rinv[m];
        float4 v = e[it];
        v.x *= r; v.y *= r; v.z *= r; v.w *= r;
        *(float4*)(S + (size_t)(row0 + m) * LL + s0 + c4 * 4) = v;
        uint32_t so = sw128((uint32_t)(m * 128 + c4 * 8));
        half hx = __float2half_rn(v.x), hy = __float2half_rn(v.y);
        half hz = __float2half_rn(v.z), hw = __float2half_rn(v.w);
        *(uint2*)(Ph + so) = make_uint2(pack2h(hx, hy), pack2h(hz, hw));
        *(uint2*)(Pl + so) = make_uint2(
            pack2h(__float2half_rn(v.x - __half2float(hx)),
                   __float2half_rn(v.y - __half2float(hy))),
            pack2h(__float2half_rn(v.z - __half2float(hz)),
                   __float2half_rn(v.w - __half2float(hw))));
    }
    #pragma unroll
    for (int it = 0; it < 4; it++) {
        int flat = it * 256 + tid;      // 1024 float4 = 64 x 16
        int c4 = flat & 15;
        int s  = flat >> 4;
        float4 w = vv[it];
        uint32_t so = sw128((uint32_t)(s * 128 + c4 * 8));
        half vx = __float2half_rn(w.x), vy = __float2half_rn(w.y);
        half vz = __float2half_rn(w.z), vw = __float2half_rn(w.w);
        *(uint2*)(Vh + so) = make_uint2(pack2h(vx, vy), pack2h(vz, vw));
        *(uint2*)(Vl + so) = make_uint2(
            pack2h(__float2half_rn(w.x - __half2float(vx)),
                   __float2half_rn(w.y - __half2float(vy))),
            pack2h(__float2half_rn(w.z - __half2float(vz)),
                   __float2half_rn(w.w - __half2float(vw))));
    }
}

__global__ __launch_bounds__(256, 2)
void k_av(const float* __restrict__ V, float* __restrict__ series,
          float* __restrict__ outV) {
    extern __shared__ __align__(1024) char avsm[];
    const int bh = blockIdx.y;
    const int b  = bh >> 3;
    const int h  = bh & 7;
    const int tid = threadIdx.x;
    const int wid = tid >> 5, lane = tid & 31;
    const int warp_m = wid & 3, warp_n = wid >> 2;
    const int m0 = warp_m * 32, n0 = warp_n * 32;
    const int g = lane >> 2, t = lane & 3;

    float* rinv = (float*)avsm;
    const uint32_t smb = smem_u32(avsm);

    float* S = series + (size_t)bh * LL * LL;
    const float* Vg = V + (size_t)b * LL * (HH * DD) + h * DD;

    // ldmatrix lane-address components
    const int a_row = (lane & 7) + ((lane >> 3) & 1) * 8;
    const int a_c16 = (lane >> 4) & 1;
    // B via ldmatrix.trans from [s][d]: m0:k0-7@n0 m1:k8-15@n0 m2:k0-7@n8 m3:k8-15@n8
    const int v_row = (lane & 7) + ((lane >> 3) & 1) * 8;
    const int v_n8  = (lane >> 4) & 1;

    uint32_t offA[2], offVb[2];
    #pragma unroll
    for (int im = 0; im < 2; im++)
        offA[im] = (uint32_t)((m0 + im * 16 + a_row) * 128 + a_c16 * 16);
    #pragma unroll
    for (int in16 = 0; in16 < 2; in16++)
        offVb[in16] = (uint32_t)(v_row * 128 + n0 * 2 + in16 * 32 + v_n8 * 16);

    const int mts[2] = { (int)blockIdx.x, 7 - (int)blockIdx.x };

    #pragma unroll 1
    for (int tt = 0; tt < 2; tt++) {
        const int mt = mts[tt];
        const int row0 = mt * 128;
        const int nchunks = 2 * (mt + 1);   // s-chunks of 64

        __syncthreads();
        if (tid < 128) {
            float s = 0.f;
            for (int nt = 0; nt <= mt; nt++)
                s += g_partial[((size_t)bh * LL + row0 + tid) * 8 + nt];
            rinv[tid] = 1.0f / s;
        }
        __syncthreads();

        float c[2][4][4];
        #pragma unroll
        for (int im = 0; im < 2; im++)
            #pragma unroll
            for (int in = 0; in < 4; in++)
                #pragma unroll
                for (int q = 0; q < 4; q++) c[im][in][q] = 0.f;

        float4 e[8], vv[4];

        {   // prolog: chunk 0 -> buffer 0
            const int s0 = mt * 128;
            #pragma unroll
            for (int it = 0; it < 8; it++) {
                int flat = it * 256 + tid;
                int c4 = flat & 15;
                int m  = flat >> 4;
                e[it] = *(const float4*)(S + (size_t)(row0 + m) * LL + s0 + c4 * 4);
            }
            #pragma unroll
            for (int it = 0; it < 4; it++) {
                int flat = it * 256 + tid;
                int c4 = flat & 15;
                int s  = flat >> 4;
                vv[it] = *(const float4*)(Vg + (size_t)(s0 + s) * 512 + c4 * 4);
            }
            av_stage(e, vv, S, rinv, avsm + AV_BUF0, row0, s0, tid);
        }
        __syncthreads();

        for (int cc = 0; cc < nchunks; cc++) {
            const int buf = cc & 1;
            const bool more = (cc + 1 < nchunks);
            int s0n = 0;
            if (more) {
                const int cn = cc + 1;
                const int ntn = mt - (cn >> 1);
                s0n = ntn * 128 + (cn & 1) * 64;
                #pragma unroll
                for (int it = 0; it < 8; it++) {
                    int flat = it * 256 + tid;
                    int c4 = flat & 15;
                    int m  = flat >> 4;
                    e[it] = *(const float4*)(S + (size_t)(row0 + m) * LL + s0n + c4 * 4);
                }
                #pragma unroll
                for (int it = 0; it < 4; it++) {
                    int flat = it * 256 + tid;
                    int c4 = flat & 15;
                    int s  = flat >> 4;
                    vv[it] = *(const float4*)(Vg + (size_t)(s0n + s) * 512 + c4 * 4);
                }
            }

            // ---- compute current buffer ----
            {
                const uint32_t base = smb + AV_BUF0 + buf * AV_BUFSZ;
                #pragma unroll
                for (int ks = 0; ks < 4; ks++) {
                    const uint32_t ko = ks * 32;        // A k-byte offset
                    const uint32_t vr = ks * 2048;      // V row offset (16 rows)
                    U4 A[2], Bh[2], Bl[2];
                    #pragma unroll
                    for (int in16 = 0; in16 < 2; in16++)
                        Bh[in16] = ldmx4t(base + AV_VHO + sw128(offVb[in16] + vr));
                    #pragma unroll
                    for (int im = 0; im < 2; im++)
                        A[im] = ldmx4(base + AV_PHO + sw128(offA[im] + ko));
                    #pragma unroll
                    for (int im = 0; im < 2; im++) {
                        mma16816(c[im][0], A[im], Bh[0].x, Bh[0].y);
                        mma16816(c[im][1], A[im], Bh[0].z, Bh[0].w);
                        mma16816(c[im][2], A[im], Bh[1].x, Bh[1].y);
                        mma16816(c[im][3], A[im], Bh[1].z, Bh[1].w);
                    }
                    #pragma unroll
                    for (int in16 = 0; in16 < 2; in16++)
                        Bl[in16] = ldmx4t(base + AV_VLO + sw128(offVb[in16] + vr));
                    #pragma unroll
                    for (int im = 0; im < 2; im++) {
                        mma16816(c[im][0], A[im], Bl[0].x, Bl[0].y);
                        mma16816(c[im][1], A[im], Bl[0].z, Bl[0].w);
                        mma16816(c[im][2], A[im], Bl[1].x, Bl[1].y);
                        mma16816(c[im][3], A[im], Bl[1].z, Bl[1].w);
                    }
                    #pragma unroll
                    for (int im = 0; im < 2; im++)
                        A[im] = ldmx4(base + AV_PLO + sw128(offA[im] + ko));
                    #pragma unroll
                    for (int im = 0; im < 2; im++) {
                        mma16816(c[im][0], A[im], Bh[0].x, Bh[0].y);
                        mma16816(c[im][1], A[im], Bh[0].z, Bh[0].w);
                        mma16816(c[im][2], A[im], Bh[1].x, Bh[1].y);
                        mma16816(c[im][3], A[im], Bh[1].z, Bh[1].w);
                    }
                }
            }

            if (more)
                av_stage(e, vv, S, rinv, avsm + AV_BUF0 + (buf ^ 1) * AV_BUFSZ,
                         row0, s0n, tid);
            __syncthreads();
        }

        // ---- output O tile ----
        float* Og = outV + (size_t)b * LL * (HH * DD) + h * DD;
        #pragma unroll
        for (int im = 0; im < 2; im++) {
            const int rowA = row0 + m0 + im * 16 + g;
            const int rowB = rowA + 8;
            #pragma unroll
            for (int in = 0; in < 4; in++) {
                const int col = n0 + in * 8 + 2 * t;
                *(float2*)(Og + (size_t)rowA * 512 + col) =
                    make_float2(c[im][in][0], c[im][in][1]);
                *(float2*)(Og + (size_t)rowB * 512 + col) =
                    make_float2(c[im][in][2], c[im][in][3]);
            }
        }
    }
}

// ---------------------------------------------------------------------------
// Kernel 3: prior association (MUFU-bound, ~20us; unchanged).
// ---------------------------------------------------------------------------
__global__ __launch_bounds__(256)
void k_prior(const float* __restrict__ sigma, float* __restrict__ prior) {
    const int b  = blockIdx.y;
    const int i0 = blockIdx.x * 32;
    const int tid = threadIdx.x;

    __shared__ float rl[8][1024];
    __shared__ float red[8];

    for (int idx = tid; idx < 8 * 1024; idx += 256) {
        int h = idx >> 10;
        int s = idx & 1023;
        rl[h][s] = -1.0f / sigma[((size_t)b * 8 + h) * 1024 + s];
    }
    __syncthreads();

    const int lane = tid & 31, wid = tid >> 5;

    for (int ii = 0; ii < 32; ii++) {
        const int i = i0 + ii;
        float p[4];
        float sum = 0.f;
        #pragma unroll
        for (int j = 0; j < 4; j++) {
            const int s = tid + j * 256;
            const float d = (float)((i > s) ? (i - s) : (s - i));
            float a = 0.f;
            #pragma unroll
            for (int h = 0; h < 8; h++)
                a += __expf(d * rl[h][s]);
            p[j] = a;
            sum += a;
        }
        #pragma unroll
        for (int off = 16; off; off >>= 1)
            sum += __shfl_xor_sync(0xffffffffu, sum, off);
        if (lane == 0) red[wid] = sum;
        __syncthreads();
        float tot = 0.f;
        #pragma unroll
        for (int w = 0; w < 8; w++) tot += red[w];
        const float inv = 1.0f / tot;
        float* dst = prior + (size_t)(b * 1024 + i) * 1024;
        #pragma unroll
        for (int j = 0; j < 4; j++)
            dst[tid + j * 256] = p[j] * inv;
        __syncthreads();
    }
}

// ---------------------------------------------------------------------------
extern "C" void kernel_launch(void* const* d_in, const int* in_sizes, int n_in,
                              void* d_out, int out_size) {
    (void)in_sizes; (void)n_in; (void)out_size;
    const float* Q   = (const float*)d_in[0];
    const float* K   = (const float*)d_in[1];
    const float* V   = (const float*)d_in[2];
    const float* sig = (const float*)d_in[3];
    float* out    = (float*)d_out;
    float* outV   = out;                 // (B,L,H,D)
    float* series = out + OFF_SERIES;    // (B,H,L,S)
    float* prior  = out + OFF_PRIOR;     // (B,L,S)

    cudaFuncSetAttribute(k_scores, cudaFuncAttributeMaxDynamicSharedMemorySize,
                         KS_SMEM);
    cudaFuncSetAttribute(k_av, cudaFuncAttributeMaxDynamicSharedMemorySize,
                         AV_SMEM);

    k_scores<<<dim3(8, 8, Bb * HH), 256, KS_SMEM>>>(Q, K, series);
    k_av    <<<dim3(4, Bb * HH),   256, AV_SMEM>>>(V, series, outV);
    k_prior <<<dim3(32, Bb),       256>>>(sig, prior);
}

// round 11
// speedup vs baseline: 2.7417x; 1.0514x over previous
#include <cuda_runtime.h>
#include <cuda_bf16.h>
#include <cuda_fp16.h>
#include <cstdint>

// Problem constants
#define Bb 8
#define LL 1024
#define HH 8
#define EE 64
#define DD 64
#define SCALE 0.125f   // 1/sqrt(64)

// Output layout (concatenated flattened tuple):
//   V:      (B,L,H,D)   at 0              size 4,194,304
//   series: (B,H,L,S)   at 4,194,304      size 67,108,864
//   prior:  (B,L,S)     at 71,303,168     size 8,388,608
#define OFF_SERIES 4194304
#define OFF_PRIOR  71303168

// Scratch: per-(b,h,row,ntile) partial row sums of unnormalized exp scores.
__device__ float g_partial[Bb * HH * LL * 8];  // 2 MB

// ---------------- warp-MMA helpers (sm_80-era PTX, sm_103-portable) --------
struct U4 { uint32_t x, y, z, w; };

__device__ __forceinline__ U4 ldmx4(uint32_t a) {
    U4 r;
    asm volatile("ldmatrix.sync.aligned.m8n8.x4.shared.b16 {%0,%1,%2,%3}, [%4];"
                 : "=r"(r.x), "=r"(r.y), "=r"(r.z), "=r"(r.w) : "r"(a));
    return r;
}
__device__ __forceinline__ U4 ldmx4t(uint32_t a) {
    U4 r;
    asm volatile("ldmatrix.sync.aligned.m8n8.x4.trans.shared.b16 {%0,%1,%2,%3}, [%4];"
                 : "=r"(r.x), "=r"(r.y), "=r"(r.z), "=r"(r.w) : "r"(a));
    return r;
}
__device__ __forceinline__ void mma16816(float* c, const U4& a,
                                         uint32_t b0, uint32_t b1) {
    asm volatile("mma.sync.aligned.m16n8k16.row.col.f32.f16.f16.f32 "
                 "{%0,%1,%2,%3}, {%4,%5,%6,%7}, {%8,%9}, {%0,%1,%2,%3};"
                 : "+f"(c[0]), "+f"(c[1]), "+f"(c[2]), "+f"(c[3])
                 : "r"(a.x), "r"(a.y), "r"(a.z), "r"(a.w), "r"(b0), "r"(b1));
}
__device__ __forceinline__ uint32_t pack2h(half a, half b) {
    return (uint32_t)__half_as_ushort(a) | ((uint32_t)__half_as_ushort(b) << 16);
}
__device__ __forceinline__ uint32_t smem_u32(const void* p) {
    uint32_t a;
    asm("{ .reg .u64 t; cvta.to.shared.u64 t, %1; cvt.u32.u64 %0, t; }"
        : "=r"(a) : "l"(p));
    return a;
}
// SW128 swizzle (Swizzle<3,4,3>) on byte offsets within a 128B-row tile
__device__ __forceinline__ uint32_t sw128(uint32_t off) {
    return off ^ ((off >> 3) & 0x70);
}

// ===========================================================================
// Kernel 1 (HMMA): E = exp(scale * Q K^T) for causal tiles.
// R11: direct epilogue stores (no smem staging round-trip).
// ===========================================================================
#define SMQ_H 0
#define SMQ_L 16384
#define SMK_H 32768
#define SMK_L 49152
#define KS_SMEM 65536

__global__ __launch_bounds__(256, 2)
void k_scores(const float* __restrict__ Q, const float* __restrict__ K,
              float* __restrict__ series) {
    extern __shared__ __align__(1024) char dsm[];
    const int nt = blockIdx.x;
    const int mt = blockIdx.y;
    const int bh = blockIdx.z;          // b*8 + h
    const int b  = bh >> 3;
    const int h  = bh & 7;
    const int tid = threadIdx.x;

    float* S = series + (size_t)bh * LL * LL;
    const int row0 = mt * 128, col0 = nt * 128;

    if (nt > mt) {
        const float4 z = make_float4(0.f, 0.f, 0.f, 0.f);
        #pragma unroll
        for (int i = 0; i < 16; i++) {
            int flat = i * 256 + tid;
            int r = flat >> 5;
            int c = (flat & 31) << 2;
            *(float4*)(S + (size_t)(row0 + r) * LL + col0 + c) = z;
        }
        return;
    }

    __shared__ float rs[128][4];   // per-(row, warp_n) partial sums

    const uint32_t smb = smem_u32(dsm);
    const int wid = tid >> 5, lane = tid & 31;
    const int warp_m = wid & 1, warp_n = wid >> 1;
    const int m0 = warp_m * 64, n0w = warp_n * 32;
    const int g = lane >> 2, t = lane & 3;

    const float* Qg = Q + (size_t)b * LL * (HH * EE) + h * EE;  // + l*512 + e
    const float* Kg = K + (size_t)b * LL * (HH * EE) + h * EE;
    #pragma unroll
    for (int it = 0; it < 8; it++) {
        int flat = it * 256 + tid;      // 2048 float4 per matrix
        int c4 = flat & 15;
        int r  = flat >> 4;
        uint32_t so = sw128((uint32_t)(r * 128 + c4 * 8));

        float4 v = *(const float4*)(Qg + (size_t)(row0 + r) * 512 + c4 * 4);
        half hx = __float2half_rn(v.x), hy = __float2half_rn(v.y);
        half hz = __float2half_rn(v.z), hw = __float2half_rn(v.w);
        *(uint2*)(dsm + SMQ_H + so) = make_uint2(pack2h(hx, hy), pack2h(hz, hw));
        *(uint2*)(dsm + SMQ_L + so) = make_uint2(
            pack2h(__float2half_rn(v.x - __half2float(hx)),
                   __float2half_rn(v.y - __half2float(hy))),
            pack2h(__float2half_rn(v.z - __half2float(hz)),
                   __float2half_rn(v.w - __half2float(hw))));

        float4 w = *(const float4*)(Kg + (size_t)(col0 + r) * 512 + c4 * 4);
        half kx = __float2half_rn(w.x), ky = __float2half_rn(w.y);
        half kz = __float2half_rn(w.z), kw = __float2half_rn(w.w);
        *(uint2*)(dsm + SMK_H + so) = make_uint2(pack2h(kx, ky), pack2h(kz, kw));
        *(uint2*)(dsm + SMK_L + so) = make_uint2(
            pack2h(__float2half_rn(w.x - __half2float(kx)),
                   __float2half_rn(w.y - __half2float(ky))),
            pack2h(__float2half_rn(w.z - __half2float(kz)),
                   __float2half_rn(w.w - __half2float(kw))));
    }
    __syncthreads();

    const int a_row = (lane & 7) + ((lane >> 3) & 1) * 8;
    const int a_c16 = (lane >> 4) & 1;
    const int b_row = (lane & 7) + ((lane >> 4) & 1) * 8;
    const int b_c16 = (lane >> 3) & 1;

    uint32_t offA[4], offB[2];
    #pragma unroll
    for (int im = 0; im < 4; im++)
        offA[im] = (uint32_t)((m0 + im * 16 + a_row) * 128 + a_c16 * 16);
    #pragma unroll
    for (int hb = 0; hb < 2; hb++)
        offB[hb] = (uint32_t)((n0w + hb * 16 + b_row) * 128 + b_c16 * 16);

    float c[4][4][4];
    #pragma unroll
    for (int im = 0; im < 4; im++)
        #pragma unroll
        for (int in = 0; in < 4; in++)
            #pragma unroll
            for (int q = 0; q < 4; q++) c[im][in][q] = 0.f;

    #pragma unroll
    for (int ks = 0; ks < 4; ks++) {
        const uint32_t ko = ks * 32;
        U4 A[4], Bh[2], Bl[2];
        #pragma unroll
        for (int hb = 0; hb < 2; hb++)
            Bh[hb] = ldmx4(smb + SMK_H + sw128(offB[hb] + ko));
        #pragma unroll
        for (int im = 0; im < 4; im++)
            A[im] = ldmx4(smb + SMQ_H + sw128(offA[im] + ko));
        #pragma unroll
        for (int im = 0; im < 4; im++) {
            mma16816(c[im][0], A[im], Bh[0].x, Bh[0].y);
            mma16816(c[im][1], A[im], Bh[0].z, Bh[0].w);
            mma16816(c[im][2], A[im], Bh[1].x, Bh[1].y);
            mma16816(c[im][3], A[im], Bh[1].z, Bh[1].w);
        }
        #pragma unroll
        for (int hb = 0; hb < 2; hb++)
            Bl[hb] = ldmx4(smb + SMK_L + sw128(offB[hb] + ko));
        #pragma unroll
        for (int im = 0; im < 4; im++) {
            mma16816(c[im][0], A[im], Bl[0].x, Bl[0].y);
            mma16816(c[im][1], A[im], Bl[0].z, Bl[0].w);
            mma16816(c[im][2], A[im], Bl[1].x, Bl[1].y);
            mma16816(c[im][3], A[im], Bl[1].z, Bl[1].w);
        }
        #pragma unroll
        for (int im = 0; im < 4; im++)
            A[im] = ldmx4(smb + SMQ_L + sw128(offA[im] + ko));
        #pragma unroll
        for (int im = 0; im < 4; im++) {
            mma16816(c[im][0], A[im], Bh[0].x, Bh[0].y);
            mma16816(c[im][1], A[im], Bh[0].z, Bh[0].w);
            mma16816(c[im][2], A[im], Bh[1].x, Bh[1].y);
            mma16816(c[im][3], A[im], Bh[1].z, Bh[1].w);
        }
    }

    // ---- epilogue: mask + exp in regs, rowsums, DIRECT float2 stores ----
    #pragma unroll
    for (int im = 0; im < 4; im++) {
        const int lrA = m0 + im * 16 + g;
        const int lrB = lrA + 8;
        const int rowA = row0 + lrA, rowB = row0 + lrB;
        float sA = 0.f, sB = 0.f;
        #pragma unroll
        for (int in = 0; in < 4; in++) {
            const int cb = n0w + in * 8 + 2 * t;
            const int colX = col0 + cb, colY = colX + 1;
            float e0 = (colX <= rowA) ? __expf(SCALE * c[im][in][0]) : 0.f;
            float e1 = (colY <= rowA) ? __expf(SCALE * c[im][in][1]) : 0.f;
            float e2 = (colX <= rowB) ? __expf(SCALE * c[im][in][2]) : 0.f;
            float e3 = (colY <= rowB) ? __expf(SCALE * c[im][in][3]) : 0.f;
            sA += e0 + e1; sB += e2 + e3;
            *(float2*)(S + (size_t)rowA * LL + colX) = make_float2(e0, e1);
            *(float2*)(S + (size_t)rowB * LL + colX) = make_float2(e2, e3);
        }
        sA += __shfl_xor_sync(0xffffffffu, sA, 1);
        sA += __shfl_xor_sync(0xffffffffu, sA, 2);
        sB += __shfl_xor_sync(0xffffffffu, sB, 1);
        sB += __shfl_xor_sync(0xffffffffu, sB, 2);
        if (t == 0) { rs[lrA][warp_n] = sA; rs[lrB][warp_n] = sB; }
    }
    __syncthreads();

    if (tid < 128)
        g_partial[((size_t)bh * LL + row0 + tid) * 8 + nt] =
            rs[tid][0] + rs[tid][1] + rs[tid][2] + rs[tid][3];
}

// ===========================================================================
// Kernel 2 (HMMA): normalize series in-place (P = E/rowsum) and O = P @ V.
// R11: unpaired tiles, 512 CTAs scheduled big-tile-first for balance.
// s-chunks of 64; double-buffered fp16 hi/lo staging; 1 sync/chunk.
// ===========================================================================
#define AV_BUF0   1024
#define AV_BUFSZ  49152
#define AV_PHO    0
#define AV_PLO    16384
#define AV_VHO    32768
#define AV_VLO    40960
#define AV_SMEM   (1024 + 2 * 49152)   // 99328 B

__device__ __forceinline__ void av_stage(
    const float4* e, const float4* vv, float* __restrict__ S,
    const float* __restrict__ rinv, char* __restrict__ buf,
    int row0, int s0, int tid) {
    char* Ph = buf + AV_PHO;
    char* Pl = buf + AV_PLO;
    char* Vh = buf + AV_VHO;
    char* Vl = buf + AV_VLO;
    #pragma unroll
    for (int it = 0; it < 8; it++) {
        int flat = it * 256 + tid;      // 2048 float4 = 128 x 16
        int c4 = flat & 15;
        int m  = flat >> 4;
        float r = rinv[m];
        float4 v = e[it];
        v.x *= r; v.y *= r; v.z *= r; v.w *= r;
        *(float4*)(S + (size_t)(row0 + m) * LL + s0 + c4 * 4) = v;
        uint32_t so = sw128((uint32_t)(m * 128 + c4 * 8));
        half hx = __float2half_rn(v.x), hy = __float2half_rn(v.y);
        half hz = __float2half_rn(v.z), hw = __float2half_rn(v.w);
        *(uint2*)(Ph + so) = make_uint2(pack2h(hx, hy), pack2h(hz, hw));
        *(uint2*)(Pl + so) = make_uint2(
            pack2h(__float2half_rn(v.x - __half2float(hx)),
                   __float2half_rn(v.y - __half2float(hy))),
            pack2h(__float2half_rn(v.z - __half2float(hz)),
                   __float2half_rn(v.w - __half2float(hw))));
    }
    #pragma unroll
    for (int it = 0; it < 4; it++) {
        int flat = it * 256 + tid;      // 1024 float4 = 64 x 16
        int c4 = flat & 15;
        int s  = flat >> 4;
        float4 w = vv[it];
        uint32_t so = sw128((uint32_t)(s * 128 + c4 * 8));
        half vx = __float2half_rn(w.x), vy = __float2half_rn(w.y);
        half vz = __float2half_rn(w.z), vw = __float2half_rn(w.w);
        *(uint2*)(Vh + so) = make_uint2(pack2h(vx, vy), pack2h(vz, vw));
        *(uint2*)(Vl + so) = make_uint2(
            pack2h(__float2half_rn(w.x - __half2float(vx)),
                   __float2half_rn(w.y - __half2float(vy))),
            pack2h(__float2half_rn(w.z - __half2float(vz)),
                   __float2half_rn(w.w - __half2float(vw))));
    }
}

__global__ __launch_bounds__(256, 2)
void k_av(const float* __restrict__ V, float* __restrict__ series,
          float* __restrict__ outV) {
    extern __shared__ __align__(1024) char avsm[];
    const int bx = blockIdx.x;
    const int mt = 7 - (bx >> 6);       // big tiles first
    const int bh = bx & 63;
    const int b  = bh >> 3;
    const int h  = bh & 7;
    const int tid = threadIdx.x;
    const int wid = tid >> 5, lane = tid & 31;
    const int warp_m = wid & 3, warp_n = wid >> 2;
    const int m0 = warp_m * 32, n0 = warp_n * 32;
    const int g = lane >> 2, t = lane & 3;

    float* rinv = (float*)avsm;
    const uint32_t smb = smem_u32(avsm);

    float* S = series + (size_t)bh * LL * LL;
    const float* Vg = V + (size_t)b * LL * (HH * DD) + h * DD;

    const int a_row = (lane & 7) + ((lane >> 3) & 1) * 8;
    const int a_c16 = (lane >> 4) & 1;
    const int v_row = (lane & 7) + ((lane >> 3) & 1) * 8;
    const int v_n8  = (lane >> 4) & 1;

    uint32_t offA[2], offVb[2];
    #pragma unroll
    for (int im = 0; im < 2; im++)
        offA[im] = (uint32_t)((m0 + im * 16 + a_row) * 128 + a_c16 * 16);
    #pragma unroll
    for (int in16 = 0; in16 < 2; in16++)
        offVb[in16] = (uint32_t)(v_row * 128 + n0 * 2 + in16 * 32 + v_n8 * 16);

    const int row0 = mt * 128;
    const int nchunks = 2 * (mt + 1);   // s-chunks of 64

    if (tid < 128) {
        float s = 0.f;
        for (int nt = 0; nt <= mt; nt++)
            s += g_partial[((size_t)bh * LL + row0 + tid) * 8 + nt];
        rinv[tid] = 1.0f / s;
    }
    __syncthreads();

    float c[2][4][4];
    #pragma unroll
    for (int im = 0; im < 2; im++)
        #pragma unroll
        for (int in = 0; in < 4; in++)
            #pragma unroll
            for (int q = 0; q < 4; q++) c[im][in][q] = 0.f;

    float4 e[8], vv[4];

    {   // prolog: chunk 0 -> buffer 0
        const int s0 = mt * 128;
        #pragma unroll
        for (int it = 0; it < 8; it++) {
            int flat = it * 256 + tid;
            int c4 = flat & 15;
            int m  = flat >> 4;
            e[it] = *(const float4*)(S + (size_t)(row0 + m) * LL + s0 + c4 * 4);
        }
        #pragma unroll
        for (int it = 0; it < 4; it++) {
            int flat = it * 256 + tid;
            int c4 = flat & 15;
            int s  = flat >> 4;
            vv[it] = *(const float4*)(Vg + (size_t)(s0 + s) * 512 + c4 * 4);
        }
        av_stage(e, vv, S, rinv, avsm + AV_BUF0, row0, s0, tid);
    }
    __syncthreads();

    for (int cc = 0; cc < nchunks; cc++) {
        const int buf = cc & 1;
        const bool more = (cc + 1 < nchunks);
        int s0n = 0;
        if (more) {
            const int cn = cc + 1;
            const int ntn = mt - (cn >> 1);
            s0n = ntn * 128 + (cn & 1) * 64;
            #pragma unroll
            for (int it = 0; it < 8; it++) {
                int flat = it * 256 + tid;
                int c4 = flat & 15;
                int m  = flat >> 4;
                e[it] = *(const float4*)(S + (size_t)(row0 + m) * LL + s0n + c4 * 4);
            }
            #pragma unroll
            for (int it = 0; it < 4; it++) {
                int flat = it * 256 + tid;
                int c4 = flat & 15;
                int s  = flat >> 4;
                vv[it] = *(const float4*)(Vg + (size_t)(s0n + s) * 512 + c4 * 4);
            }
        }

        // ---- compute current buffer ----
        {
            const uint32_t base = smb + AV_BUF0 + buf * AV_BUFSZ;
            #pragma unroll
            for (int ks = 0; ks < 4; ks++) {
                const uint32_t ko = ks * 32;        // A k-byte offset
                const uint32_t vr = ks * 2048;      // V row offset (16 rows)
                U4 A[2], Bh[2], Bl[2];
                #pragma unroll
                for (int in16 = 0; in16 < 2; in16++)
                    Bh[in16] = ldmx4t(base + AV_VHO + sw128(offVb[in16] + vr));
                #pragma unroll
                for (int im = 0; im < 2; im++)
                    A[im] = ldmx4(base + AV_PHO + sw128(offA[im] + ko));
                #pragma unroll
                for (int im = 0; im < 2; im++) {
                    mma16816(c[im][0], A[im], Bh[0].x, Bh[0].y);
                    mma16816(c[im][1], A[im], Bh[0].z, Bh[0].w);
                    mma16816(c[im][2], A[im], Bh[1].x, Bh[1].y);
                    mma16816(c[im][3], A[im], Bh[1].z, Bh[1].w);
                }
                #pragma unroll
                for (int in16 = 0; in16 < 2; in16++)
                    Bl[in16] = ldmx4t(base + AV_VLO + sw128(offVb[in16] + vr));
                #pragma unroll
                for (int im = 0; im < 2; im++) {
                    mma16816(c[im][0], A[im], Bl[0].x, Bl[0].y);
                    mma16816(c[im][1], A[im], Bl[0].z, Bl[0].w);
                    mma16816(c[im][2], A[im], Bl[1].x, Bl[1].y);
                    mma16816(c[im][3], A[im], Bl[1].z, Bl[1].w);
                }
                #pragma unroll
                for (int im = 0; im < 2; im++)
                    A[im] = ldmx4(base + AV_PLO + sw128(offA[im] + ko));
                #pragma unroll
                for (int im = 0; im < 2; im++) {
                    mma16816(c[im][0], A[im], Bh[0].x, Bh[0].y);
                    mma16816(c[im][1], A[im], Bh[0].z, Bh[0].w);
                    mma16816(c[im][2], A[im], Bh[1].x, Bh[1].y);
                    mma16816(c[im][3], A[im], Bh[1].z, Bh[1].w);
                }
            }
        }

        if (more)
            av_stage(e, vv, S, rinv, avsm + AV_BUF0 + (buf ^ 1) * AV_BUFSZ,
                     row0, s0n, tid);
        __syncthreads();
    }

    // ---- output O tile ----
    float* Og = outV + (size_t)b * LL * (HH * DD) + h * DD;
    #pragma unroll
    for (int im = 0; im < 2; im++) {
        const int rowA = row0 + m0 + im * 16 + g;
        const int rowB = rowA + 8;
        #pragma unroll
        for (int in = 0; in < 4; in++) {
            const int col = n0 + in * 8 + 2 * t;
            *(float2*)(Og + (size_t)rowA * 512 + col) =
                make_float2(c[im][in][0], c[im][in][1]);
            *(float2*)(Og + (size_t)rowB * 512 + col) =
                make_float2(c[im][in][2], c[im][in][3]);
        }
    }
}

// ---------------------------------------------------------------------------
// Kernel 3: prior association (MUFU-bound, ~20us; unchanged).
// ---------------------------------------------------------------------------
__global__ __launch_bounds__(256)
void k_prior(const float* __restrict__ sigma, float* __restrict__ prior) {
    const int b  = blockIdx.y;
    const int i0 = blockIdx.x * 32;
    const int tid = threadIdx.x;

    __shared__ float rl[8][1024];
    __shared__ float red[8];

    for (int idx = tid; idx < 8 * 1024; idx += 256) {
        int h = idx >> 10;
        int s = idx & 1023;
        rl[h][s] = -1.0f / sigma[((size_t)b * 8 + h) * 1024 + s];
    }
    __syncthreads();

    const int lane = tid & 31, wid = tid >> 5;

    for (int ii = 0; ii < 32; ii++) {
        const int i = i0 + ii;
        float p[4];
        float sum = 0.f;
        #pragma unroll
        for (int j = 0; j < 4; j++) {
            const int s = tid + j * 256;
            const float d = (float)((i > s) ? (i - s) : (s - i));
            float a = 0.f;
            #pragma unroll
            for (int h = 0; h < 8; h++)
                a += __expf(d * rl[h][s]);
            p[j] = a;
            sum += a;
        }
        #pragma unroll
        for (int off = 16; off; off >>= 1)
            sum += __shfl_xor_sync(0xffffffffu, sum, off);
        if (lane == 0) red[wid] = sum;
        __syncthreads();
        float tot = 0.f;
        #pragma unroll
        for (int w = 0; w < 8; w++) tot += red[w];
        const float inv = 1.0f / tot;
        float* dst = prior + (size_t)(b * 1024 + i) * 1024;
        #pragma unroll
        for (int j = 0; j < 4; j++)
            dst[tid + j * 256] = p[j] * inv;
        __syncthreads();
    }
}

// ---------------------------------------------------------------------------
extern "C" void kernel_launch(void* const* d_in, const int* in_sizes, int n_in,
                              void* d_out, int out_size) {
    (void)in_sizes; (void)n_in; (void)out_size;
    const float* Q   = (const float*)d_in[0];
    const float* K   = (const float*)d_in[1];
    const float* V   = (const float*)d_in[2];
    const float* sig = (const float*)d_in[3];
    float* out    = (float*)d_out;
    float* outV   = out;                 // (B,L,H,D)
    float* series = out + OFF_SERIES;    // (B,H,L,S)
    float* prior  = out + OFF_PRIOR;     // (B,L,S)

    cudaFuncSetAttribute(k_scores, cudaFuncAttributeMaxDynamicSharedMemorySize,
                         KS_SMEM);
    cudaFuncSetAttribute(k_av, cudaFuncAttributeMaxDynamicSharedMemorySize,
                         AV_SMEM);

    k_scores<<<dim3(8, 8, Bb * HH), 256, KS_SMEM>>>(Q, K, series);
    k_av    <<<dim3(512, 1),       256, AV_SMEM>>>(V, series, outV);
    k_prior <<<dim3(32, Bb),       256>>>(sig, prior);
}